// round 11
// baseline (speedup 1.0000x reference)
#include <cuda_runtime.h>
#include <cstdint>
#include <cstddef>

// ---------------- problem constants (fixed by the dataset) ----------------
#define NN   16384      // nodes
#define NE   262144     // static edges (== NN * 16, also dynamic edge count)
#define DD   128        // node dim
#define DE   64         // edge dim
#define HH   256        // hidden
#define KK   16         // kNN

// ---------------- device scratch (allocation-free rule: __device__ globals) ----
__device__ float g_msg [(size_t)NE * 256];
__device__ float g_hid [(size_t)NE * 256];
__device__ float g_ea0 [(size_t)NE * DE];
__device__ float g_ea1 [(size_t)NE * DE];
__device__ float g_xs0 [NN * DD];
__device__ float g_xs1 [NN * DD];
__device__ float g_xd0 [NN * DD];
__device__ float g_xd1 [NN * DD];
__device__ float g_agg [NN * DD];
__device__ float g_tmpN[NN * HH];
__device__ float g_P2  [NN * HH];
__device__ float g_cat [NN * 2 * DD];
__device__ float g_sq  [NN];
__device__ float g_xT  [(size_t)DD * NN];
__device__ float g_dist[(size_t)NN * NN];
__device__ int   g_knn [NN * KK];
__device__ float g_zero[HH];          // zero-initialized bias
__device__ int   g_ei64flag;

// ---------------- edge_index dtype handling (int64 vs silently-int32) -----
__global__ void detect_ei_k(const void* p) {
    const unsigned long long* q = (const unsigned long long*)p;
    int ok = 1;
    #pragma unroll
    for (int i = 0; i < 8; i++)
        if (q[i] >= (unsigned long long)NN) ok = 0;
    g_ei64flag = ok;
}

__device__ __forceinline__ long long load_ei(const void* p, long long idx) {
    if (g_ei64flag) return ((const long long*)p)[idx];
    return (long long)((const int*)p)[idx];
}

// ---------------- tf32 helpers ----------------------------------------------
__device__ __forceinline__ float f2tf(float x) {
    uint32_t u;
    asm("cvt.rna.tf32.f32 %0, %1;" : "=r"(u) : "f"(x));
    return __uint_as_float(u);
}

#define MMA_TF32(acc, a0, a1, a2, a3, b0, b1)                                  \
    asm volatile(                                                              \
        "mma.sync.aligned.m16n8k8.row.col.f32.tf32.tf32.f32 "                  \
        "{%0,%1,%2,%3}, {%4,%5,%6,%7}, {%8,%9}, {%0,%1,%2,%3};"                \
        : "+f"(acc[0]), "+f"(acc[1]), "+f"(acc[2]), "+f"(acc[3])               \
        : "r"(a0), "r"(a1), "r"(a2), "r"(a3), "r"(b0), "r"(b1))

#define TBM 128
#define TBN 128
#define TBK 32
#define ASTR 36
#define BSTR 136
#define A_SZ (TBM * ASTR)
#define B_SZ (TBK * BSTR)
#define MMA3_SMEM_BYTES ((2 * A_SZ + 2 * B_SZ) * 4)   // 71680 B

// ---------------- 3xTF32 tensor-core GEMM (fp32-accurate) --------------------
// mode 0: relu(acc+bias) store; mode 2: acc+bias store
// mode 3: relu(acc+bias) atomicAdd into C[ei[NE+row]*N + col]
// mode 4: relu(acc+bias) atomicAdd into C[(row>>4)*N + col]
__global__ __launch_bounds__(256, 2) void mma3_gemm_k(
    const float* __restrict__ A, const float* __restrict__ B,
    const float* __restrict__ bias, float* __restrict__ C,
    int M, int K, int N, int mode, const void* __restrict__ ei)
{
    extern __shared__ float sm[];
    float* Ah = sm;
    float* Al = sm + A_SZ;
    float* Bh = sm + 2 * A_SZ;
    float* Bl = sm + 2 * A_SZ + B_SZ;

    const int tid  = threadIdx.x;
    const int lane = tid & 31;
    const int warp = tid >> 5;
    const int warp_m = warp & 1;
    const int warp_n = warp >> 1;
    const int row0 = blockIdx.y * TBM;
    const int col0 = blockIdx.x * TBN;
    const int g  = lane >> 2;
    const int tg = lane & 3;

    const int ar_ = tid >> 3, ac4 = tid & 7;
    const int bkr = tid >> 5, bc4 = tid & 31;

    float acc[4][4][4];
    #pragma unroll
    for (int mm = 0; mm < 4; mm++)
        #pragma unroll
        for (int nn = 0; nn < 4; nn++)
            #pragma unroll
            for (int r = 0; r < 4; r++) acc[mm][nn][r] = 0.f;

    const int ktiles = K / TBK;

    float4 pa[4], pb[4];
    #pragma unroll
    for (int p = 0; p < 4; p++)
        pa[p] = *(const float4*)(A + (size_t)(row0 + ar_ + 32 * p) * K + ac4 * 4);
    #pragma unroll
    for (int p = 0; p < 4; p++)
        pb[p] = *(const float4*)(B + (size_t)(bkr + 8 * p) * N + col0 + bc4 * 4);

    for (int kt = 0; kt < ktiles; kt++) {
        #pragma unroll
        for (int p = 0; p < 4; p++) {
            const float4 v = pa[p];
            float4 vh, vl;
            vh.x = f2tf(v.x); vl.x = f2tf(v.x - vh.x);
            vh.y = f2tf(v.y); vl.y = f2tf(v.y - vh.y);
            vh.z = f2tf(v.z); vl.z = f2tf(v.z - vh.z);
            vh.w = f2tf(v.w); vl.w = f2tf(v.w - vh.w);
            *(float4*)&Ah[(ar_ + 32 * p) * ASTR + ac4 * 4] = vh;
            *(float4*)&Al[(ar_ + 32 * p) * ASTR + ac4 * 4] = vl;
        }
        #pragma unroll
        for (int p = 0; p < 4; p++) {
            const float4 v = pb[p];
            float4 vh, vl;
            vh.x = f2tf(v.x); vl.x = f2tf(v.x - vh.x);
            vh.y = f2tf(v.y); vl.y = f2tf(v.y - vh.y);
            vh.z = f2tf(v.z); vl.z = f2tf(v.z - vh.z);
            vh.w = f2tf(v.w); vl.w = f2tf(v.w - vh.w);
            *(float4*)&Bh[(bkr + 8 * p) * BSTR + bc4 * 4] = vh;
            *(float4*)&Bl[(bkr + 8 * p) * BSTR + bc4 * 4] = vl;
        }
        __syncthreads();

        if (kt + 1 < ktiles) {
            const int ko = (kt + 1) * TBK;
            #pragma unroll
            for (int p = 0; p < 4; p++)
                pa[p] = *(const float4*)(A + (size_t)(row0 + ar_ + 32 * p) * K + ko + ac4 * 4);
            #pragma unroll
            for (int p = 0; p < 4; p++)
                pb[p] = *(const float4*)(B + (size_t)(ko + bkr + 8 * p) * N + col0 + bc4 * 4);
        }

        #pragma unroll
        for (int kk = 0; kk < 4; kk++) {
            const int kb = kk * 8;
            uint32_t af[4][4], bf[4][2];

            #pragma unroll
            for (int mm = 0; mm < 4; mm++) {
                const int ar = warp_m * 64 + mm * 16 + g;
                af[mm][0] = __float_as_uint(Ah[ar * ASTR + kb + tg]);
                af[mm][1] = __float_as_uint(Ah[(ar + 8) * ASTR + kb + tg]);
                af[mm][2] = __float_as_uint(Ah[ar * ASTR + kb + tg + 4]);
                af[mm][3] = __float_as_uint(Ah[(ar + 8) * ASTR + kb + tg + 4]);
            }
            #pragma unroll
            for (int nn = 0; nn < 4; nn++) {
                const int bc = warp_n * 32 + nn * 8 + g;
                bf[nn][0] = __float_as_uint(Bl[(kb + tg) * BSTR + bc]);
                bf[nn][1] = __float_as_uint(Bl[(kb + tg + 4) * BSTR + bc]);
            }
            #pragma unroll
            for (int mm = 0; mm < 4; mm++)
                #pragma unroll
                for (int nn = 0; nn < 4; nn++)
                    MMA_TF32(acc[mm][nn], af[mm][0], af[mm][1], af[mm][2], af[mm][3],
                             bf[nn][0], bf[nn][1]);
            #pragma unroll
            for (int nn = 0; nn < 4; nn++) {
                const int bc = warp_n * 32 + nn * 8 + g;
                bf[nn][0] = __float_as_uint(Bh[(kb + tg) * BSTR + bc]);
                bf[nn][1] = __float_as_uint(Bh[(kb + tg + 4) * BSTR + bc]);
            }
            #pragma unroll
            for (int mm = 0; mm < 4; mm++)
                #pragma unroll
                for (int nn = 0; nn < 4; nn++)
                    MMA_TF32(acc[mm][nn], af[mm][0], af[mm][1], af[mm][2], af[mm][3],
                             bf[nn][0], bf[nn][1]);
            #pragma unroll
            for (int mm = 0; mm < 4; mm++) {
                const int ar = warp_m * 64 + mm * 16 + g;
                af[mm][0] = __float_as_uint(Al[ar * ASTR + kb + tg]);
                af[mm][1] = __float_as_uint(Al[(ar + 8) * ASTR + kb + tg]);
                af[mm][2] = __float_as_uint(Al[ar * ASTR + kb + tg + 4]);
                af[mm][3] = __float_as_uint(Al[(ar + 8) * ASTR + kb + tg + 4]);
            }
            #pragma unroll
            for (int mm = 0; mm < 4; mm++)
                #pragma unroll
                for (int nn = 0; nn < 4; nn++)
                    MMA_TF32(acc[mm][nn], af[mm][0], af[mm][1], af[mm][2], af[mm][3],
                             bf[nn][0], bf[nn][1]);
        }
        __syncthreads();
    }

    if (mode <= 2) {
        #pragma unroll
        for (int nn = 0; nn < 4; nn++) {
            const int col = col0 + warp_n * 32 + nn * 8 + tg * 2;
            const float bv0 = bias[col], bv1 = bias[col + 1];
            #pragma unroll
            for (int mm = 0; mm < 4; mm++) {
                const int row = row0 + warp_m * 64 + mm * 16 + g;
                float2 o0, o1;
                if (mode == 0) {
                    o0.x = fmaxf(acc[mm][nn][0] + bv0, 0.f);
                    o0.y = fmaxf(acc[mm][nn][1] + bv1, 0.f);
                    o1.x = fmaxf(acc[mm][nn][2] + bv0, 0.f);
                    o1.y = fmaxf(acc[mm][nn][3] + bv1, 0.f);
                } else {
                    o0.x = acc[mm][nn][0] + bv0;
                    o0.y = acc[mm][nn][1] + bv1;
                    o1.x = acc[mm][nn][2] + bv0;
                    o1.y = acc[mm][nn][3] + bv1;
                }
                *(float2*)(C + (size_t)row * N + col)       = o0;
                *(float2*)(C + (size_t)(row + 8) * N + col) = o1;
            }
        }
    } else {
        #pragma unroll
        for (int mm = 0; mm < 4; mm++) {
            const int row = row0 + warp_m * 64 + mm * 16 + g;
            long long d0, d1;
            if (mode == 3) {
                d0 = load_ei(ei, (long long)NE + row);
                d1 = load_ei(ei, (long long)NE + row + 8);
            } else {
                d0 = row >> 4;
                d1 = (row + 8) >> 4;
            }
            #pragma unroll
            for (int nn = 0; nn < 4; nn++) {
                const int col = col0 + warp_n * 32 + nn * 8 + tg * 2;
                const float bv0 = bias[col], bv1 = bias[col + 1];
                atomicAdd(&C[d0 * N + col],     fmaxf(acc[mm][nn][0] + bv0, 0.f));
                atomicAdd(&C[d0 * N + col + 1], fmaxf(acc[mm][nn][1] + bv1, 0.f));
                atomicAdd(&C[d1 * N + col],     fmaxf(acc[mm][nn][2] + bv0, 0.f));
                atomicAdd(&C[d1 * N + col + 1], fmaxf(acc[mm][nn][3] + bv1, 0.f));
            }
        }
    }
}

// ---------------- symmetric distance GEMM (lower triangle + mirror) ----------
__global__ __launch_bounds__(256, 2) void dist_sym_k(
    const float* __restrict__ X, const float* __restrict__ XT,
    const float* __restrict__ sq, float* __restrict__ C)
{
    const int bi = blockIdx.y, bj = blockIdx.x;
    if (bj > bi) return;

    extern __shared__ float sm[];
    float* Ah = sm;
    float* Al = sm + A_SZ;
    float* Bh = sm + 2 * A_SZ;
    float* Bl = sm + 2 * A_SZ + B_SZ;

    const int tid  = threadIdx.x;
    const int lane = tid & 31;
    const int warp = tid >> 5;
    const int warp_m = warp & 1;
    const int warp_n = warp >> 1;
    const int row0 = bi * TBM;
    const int col0 = bj * TBM;
    const int g  = lane >> 2;
    const int tg = lane & 3;

    const int ar_ = tid >> 3, ac4 = tid & 7;
    const int bkr = tid >> 5, bc4 = tid & 31;

    float acc[4][4][4];
    #pragma unroll
    for (int mm = 0; mm < 4; mm++)
        #pragma unroll
        for (int nn = 0; nn < 4; nn++)
            #pragma unroll
            for (int r = 0; r < 4; r++) acc[mm][nn][r] = 0.f;

    float4 pa[4], pb[4];
    #pragma unroll
    for (int p = 0; p < 4; p++)
        pa[p] = *(const float4*)(X + (size_t)(row0 + ar_ + 32 * p) * DD + ac4 * 4);
    #pragma unroll
    for (int p = 0; p < 4; p++)
        pb[p] = *(const float4*)(XT + (size_t)(bkr + 8 * p) * NN + col0 + bc4 * 4);

    #pragma unroll
    for (int kt = 0; kt < DD / TBK; kt++) {
        #pragma unroll
        for (int p = 0; p < 4; p++) {
            const float4 v = pa[p];
            float4 vh, vl;
            vh.x = f2tf(v.x); vl.x = f2tf(v.x - vh.x);
            vh.y = f2tf(v.y); vl.y = f2tf(v.y - vh.y);
            vh.z = f2tf(v.z); vl.z = f2tf(v.z - vh.z);
            vh.w = f2tf(v.w); vl.w = f2tf(v.w - vh.w);
            *(float4*)&Ah[(ar_ + 32 * p) * ASTR + ac4 * 4] = vh;
            *(float4*)&Al[(ar_ + 32 * p) * ASTR + ac4 * 4] = vl;
        }
        #pragma unroll
        for (int p = 0; p < 4; p++) {
            const float4 v = pb[p];
            float4 vh, vl;
            vh.x = f2tf(v.x); vl.x = f2tf(v.x - vh.x);
            vh.y = f2tf(v.y); vl.y = f2tf(v.y - vh.y);
            vh.z = f2tf(v.z); vl.z = f2tf(v.z - vh.z);
            vh.w = f2tf(v.w); vl.w = f2tf(v.w - vh.w);
            *(float4*)&Bh[(bkr + 8 * p) * BSTR + bc4 * 4] = vh;
            *(float4*)&Bl[(bkr + 8 * p) * BSTR + bc4 * 4] = vl;
        }
        __syncthreads();

        if (kt + 1 < DD / TBK) {
            const int ko = (kt + 1) * TBK;
            #pragma unroll
            for (int p = 0; p < 4; p++)
                pa[p] = *(const float4*)(X + (size_t)(row0 + ar_ + 32 * p) * DD + ko + ac4 * 4);
            #pragma unroll
            for (int p = 0; p < 4; p++)
                pb[p] = *(const float4*)(XT + (size_t)(ko + bkr + 8 * p) * NN + col0 + bc4 * 4);
        }

        #pragma unroll
        for (int kk = 0; kk < 4; kk++) {
            const int kb = kk * 8;
            uint32_t af[4][4], bf[4][2];

            #pragma unroll
            for (int mm = 0; mm < 4; mm++) {
                const int ar = warp_m * 64 + mm * 16 + g;
                af[mm][0] = __float_as_uint(Ah[ar * ASTR + kb + tg]);
                af[mm][1] = __float_as_uint(Ah[(ar + 8) * ASTR + kb + tg]);
                af[mm][2] = __float_as_uint(Ah[ar * ASTR + kb + tg + 4]);
                af[mm][3] = __float_as_uint(Ah[(ar + 8) * ASTR + kb + tg + 4]);
            }
            #pragma unroll
            for (int nn = 0; nn < 4; nn++) {
                const int bc = warp_n * 32 + nn * 8 + g;
                bf[nn][0] = __float_as_uint(Bl[(kb + tg) * BSTR + bc]);
                bf[nn][1] = __float_as_uint(Bl[(kb + tg + 4) * BSTR + bc]);
            }
            #pragma unroll
            for (int mm = 0; mm < 4; mm++)
                #pragma unroll
                for (int nn = 0; nn < 4; nn++)
                    MMA_TF32(acc[mm][nn], af[mm][0], af[mm][1], af[mm][2], af[mm][3],
                             bf[nn][0], bf[nn][1]);
            #pragma unroll
            for (int nn = 0; nn < 4; nn++) {
                const int bc = warp_n * 32 + nn * 8 + g;
                bf[nn][0] = __float_as_uint(Bh[(kb + tg) * BSTR + bc]);
                bf[nn][1] = __float_as_uint(Bh[(kb + tg + 4) * BSTR + bc]);
            }
            #pragma unroll
            for (int mm = 0; mm < 4; mm++)
                #pragma unroll
                for (int nn = 0; nn < 4; nn++)
                    MMA_TF32(acc[mm][nn], af[mm][0], af[mm][1], af[mm][2], af[mm][3],
                             bf[nn][0], bf[nn][1]);
            #pragma unroll
            for (int mm = 0; mm < 4; mm++) {
                const int ar = warp_m * 64 + mm * 16 + g;
                af[mm][0] = __float_as_uint(Al[ar * ASTR + kb + tg]);
                af[mm][1] = __float_as_uint(Al[(ar + 8) * ASTR + kb + tg]);
                af[mm][2] = __float_as_uint(Al[ar * ASTR + kb + tg + 4]);
                af[mm][3] = __float_as_uint(Al[(ar + 8) * ASTR + kb + tg + 4]);
            }
            #pragma unroll
            for (int mm = 0; mm < 4; mm++)
                #pragma unroll
                for (int nn = 0; nn < 4; nn++)
                    MMA_TF32(acc[mm][nn], af[mm][0], af[mm][1], af[mm][2], af[mm][3],
                             bf[nn][0], bf[nn][1]);
        }
        __syncthreads();
    }

    #pragma unroll
    for (int nn = 0; nn < 4; nn++) {
        const int col = col0 + warp_n * 32 + nn * 8 + tg * 2;
        const float bv0 = sq[col], bv1 = sq[col + 1];
        #pragma unroll
        for (int mm = 0; mm < 4; mm++) {
            const int row = row0 + warp_m * 64 + mm * 16 + g;
            float2 o0, o1;
            o0.x = bv0 - 2.f * acc[mm][nn][0];
            o0.y = bv1 - 2.f * acc[mm][nn][1];
            o1.x = bv0 - 2.f * acc[mm][nn][2];
            o1.y = bv1 - 2.f * acc[mm][nn][3];
            *(float2*)(C + (size_t)row * NN + col)       = o0;
            *(float2*)(C + (size_t)(row + 8) * NN + col) = o1;
        }
    }

    if (bi != bj) {
        float* Sc = sm;
        #pragma unroll
        for (int mm = 0; mm < 4; mm++) {
            const int lr = warp_m * 64 + mm * 16 + g;
            const float s0 = sq[row0 + lr], s1 = sq[row0 + lr + 8];
            #pragma unroll
            for (int nn = 0; nn < 4; nn++) {
                const int lc = warp_n * 32 + nn * 8 + tg * 2;
                Sc[lc * 132 + lr]            = s0 - 2.f * acc[mm][nn][0];
                Sc[(lc + 1) * 132 + lr]      = s0 - 2.f * acc[mm][nn][1];
                Sc[lc * 132 + lr + 8]        = s1 - 2.f * acc[mm][nn][2];
                Sc[(lc + 1) * 132 + lr + 8]  = s1 - 2.f * acc[mm][nn][3];
            }
        }
        __syncthreads();
        #pragma unroll
        for (int it = 0; it < 16; it++) {
            const int lc = warp + it * 8;
            const float4 v = *(const float4*)&Sc[lc * 132 + lane * 4];
            *(float4*)(C + (size_t)(col0 + lc) * NN + row0 + lane * 4) = v;
        }
    }
}

// ---------------- fallback SIMT GEMM (used only when N % 128 != 0) ----------
#define GBM 128
#define GBN 64
#define GBK 32

__global__ __launch_bounds__(256, 2) void gemm_k(
    const float* __restrict__ A, const float* __restrict__ B,
    const float* __restrict__ bias, float* __restrict__ C,
    int M, int K, int N, int mode)
{
    __shared__ float As[GBK][GBM + 4];
    __shared__ float Bs[GBK][GBN];
    const int tid  = threadIdx.x;
    const int row0 = blockIdx.y * GBM;
    const int col0 = blockIdx.x * GBN;
    const int tr = tid >> 4;
    const int tc = tid & 15;

    float acc[8][4];
    #pragma unroll
    for (int i = 0; i < 8; i++)
        #pragma unroll
        for (int j = 0; j < 4; j++) acc[i][j] = 0.f;

    const int ktiles = K / GBK;
    for (int kt = 0; kt < ktiles; kt++) {
        #pragma unroll
        for (int p = 0; p < 4; p++) {
            int lin = tid + 256 * p;
            int r = lin >> 3, q = lin & 7;
            const float4 v = *(const float4*)(A + (size_t)(row0 + r) * K + kt * GBK + q * 4);
            As[q * 4 + 0][r] = v.x; As[q * 4 + 1][r] = v.y;
            As[q * 4 + 2][r] = v.z; As[q * 4 + 3][r] = v.w;
        }
        #pragma unroll
        for (int p = 0; p < 2; p++) {
            int lin = tid + 256 * p;
            int kr = lin >> 4, j4 = lin & 15;
            *(float4*)&Bs[kr][j4 * 4] =
                *(const float4*)(B + (size_t)(kt * GBK + kr) * N + col0 + j4 * 4);
        }
        __syncthreads();
        #pragma unroll
        for (int k = 0; k < GBK; k++) {
            float a[8], b[4];
            *(float4*)&a[0] = *(const float4*)&As[k][tr * 8];
            *(float4*)&a[4] = *(const float4*)&As[k][tr * 8 + 4];
            *(float4*)&b[0] = *(const float4*)&Bs[k][tc * 4];
            #pragma unroll
            for (int i = 0; i < 8; i++)
                #pragma unroll
                for (int j = 0; j < 4; j++)
                    acc[i][j] = fmaf(a[i], b[j], acc[i][j]);
        }
        __syncthreads();
    }

    float bv[4];
    #pragma unroll
    for (int j = 0; j < 4; j++) bv[j] = bias[col0 + tc * 4 + j];

    #pragma unroll
    for (int i = 0; i < 8; i++) {
        const int row = row0 + tr * 8 + i;
        float4 o;
        o.x = fmaxf(acc[i][0] + bv[0], 0.f);
        o.y = fmaxf(acc[i][1] + bv[1], 0.f);
        o.z = fmaxf(acc[i][2] + bv[2], 0.f);
        o.w = fmaxf(acc[i][3] + bv[3], 0.f);
        *(float4*)(C + (size_t)row * N + col0 + tc * 4) = o;
    }
}

// ---------------- fusion kernels (factored first MLP layer) ------------------
__global__ __launch_bounds__(256) void static_fuse_k(
    const float* __restrict__ eW, const float* __restrict__ P,
    const void* __restrict__ ei, float* __restrict__ hid)
{
    const int e  = blockIdx.x * 4 + (threadIdx.x >> 6);
    const int c4 = threadIdx.x & 63;
    const long long s = load_ei(ei, e);
    const long long d = load_ei(ei, (long long)NE + e);
    const float4 a = *(const float4*)(eW + (size_t)e * HH + c4 * 4);
    const float4 ps = *(const float4*)(P + (size_t)s * HH + c4 * 4);
    const float4 pd = *(const float4*)(P + (size_t)d * HH + c4 * 4);
    float4 o;
    o.x = fmaxf(a.x + ps.x - pd.x, 0.f);
    o.y = fmaxf(a.y + ps.y - pd.y, 0.f);
    o.z = fmaxf(a.z + ps.z - pd.z, 0.f);
    o.w = fmaxf(a.w + ps.w - pd.w, 0.f);
    *(float4*)(hid + (size_t)e * HH + c4 * 4) = o;
}

__global__ __launch_bounds__(256) void dyn_fuse_k(
    const float* __restrict__ P1, const float* __restrict__ P2,
    const int* __restrict__ knn, const float* __restrict__ bias,
    float* __restrict__ hid)
{
    const int e  = blockIdx.x * 4 + (threadIdx.x >> 6);
    const int c4 = threadIdx.x & 63;
    const int i = e >> 4;
    const int j = knn[e];
    const float4 p1 = *(const float4*)(P1 + (size_t)i * HH + c4 * 4);
    const float4 pi = *(const float4*)(P2 + (size_t)i * HH + c4 * 4);
    const float4 pj = *(const float4*)(P2 + (size_t)j * HH + c4 * 4);
    const float4 b  = *(const float4*)(bias + c4 * 4);
    float4 o;
    o.x = fmaxf(p1.x - pi.x + pj.x + b.x, 0.f);
    o.y = fmaxf(p1.y - pi.y + pj.y + b.y, 0.f);
    o.z = fmaxf(p1.z - pi.z + pj.z + b.z, 0.f);
    o.w = fmaxf(p1.w - pi.w + pj.w + b.w, 0.f);
    *(float4*)(hid + (size_t)e * HH + c4 * 4) = o;
}

// ---------------- small helper kernels --------------------------------------
__global__ void rownorm_k(const float* __restrict__ x, float* __restrict__ sq)
{
    const int row  = blockIdx.x * 8 + (threadIdx.x >> 5);
    const int lane = threadIdx.x & 31;
    const float* p = x + (size_t)row * DD;
    float s = 0.f;
    #pragma unroll
    for (int q = 0; q < 4; q++) { float v = p[lane + 32 * q]; s = fmaf(v, v, s); }
    #pragma unroll
    for (int o = 16; o > 0; o >>= 1) s += __shfl_xor_sync(0xffffffffu, s, o);
    if (lane == 0) sq[row] = s;
}

__global__ void transpose_k(const float* __restrict__ in, float* __restrict__ out)
{
    __shared__ float t[32][33];
    const int j0 = blockIdx.x * 32, k0 = blockIdx.y * 32;
    for (int r = threadIdx.y; r < 32; r += 8)
        t[r][threadIdx.x] = in[(size_t)(j0 + r) * DD + k0 + threadIdx.x];
    __syncthreads();
    for (int r = threadIdx.y; r < 32; r += 8)
        out[(size_t)(k0 + r) * NN + j0 + threadIdx.x] = t[threadIdx.x][r];
}

// ---------------- top-16: u64 keys, smem queues, float4 min-filtered scan ----
// 16 rows per 256-thread block; 16 threads per row, each scanning 1024 elems.
// key = ordered_u32(val) << 32 | col  -> one u64 compare = (val, idx) order.
// Sentinel = key(+inf, idx 0xFFFFFFFF) so the decoded worst value is +inf
// (NOT NaN).  Acceptance test is on the full 64-bit key, reproducing the
// reference (val, idx) tie-break exactly.
__global__ __launch_bounds__(256) void topk_k(const float* __restrict__ dist,
                                              int* __restrict__ knn)
{
    __shared__ unsigned long long sk[256 * KK];   // 32 KB
    const unsigned long long SENT = 0xFF800000FFFFFFFFull;  // (+inf, idxmax)
    const int tid = threadIdx.x;
    const int rr  = tid >> 4;          // row within block
    const int tt  = tid & 15;          // thread within row
    const int row_g = blockIdx.x * 16 + rr;
    const float* row = dist + (size_t)row_g * NN;
    const int base = tid * KK;

    #pragma unroll
    for (int q = 0; q < KK; q++) sk[base + q] = SENT;
    unsigned long long worst_key = SENT;
    float worstf = __int_as_float(0x7f800000);   // +inf

    for (int c = 0; c < NN / 64; c++) {
        const float4 v = *(const float4*)(row + c * 64 + tt * 4);
        const float mn = fminf(fminf(v.x, v.y), fminf(v.z, v.w));
        if (mn <= worstf) {
            const int j0 = c * 64 + tt * 4;
            const float vv[4] = { v.x, v.y, v.z, v.w };
            #pragma unroll
            for (int u = 0; u < 4; u++) {
                uint32_t ou = __float_as_uint(vv[u]);
                ou = (ou & 0x80000000u) ? ~ou : (ou | 0x80000000u);
                const unsigned long long key =
                    ((unsigned long long)ou << 32) | (uint32_t)(j0 + u);
                if (key < worst_key) {
                    int p = KK - 1;
                    while (p > 0 && sk[base + p - 1] > key) {
                        sk[base + p] = sk[base + p - 1];
                        p--;
                    }
                    sk[base + p] = key;
                    worst_key = sk[base + KK - 1];
                    uint32_t wo = (uint32_t)(worst_key >> 32);
                    wo = (wo & 0x80000000u) ? (wo ^ 0x80000000u) : ~wo;
                    worstf = __uint_as_float(wo);
                }
            }
        }
    }

    // merge 16 sorted lists per row (4 pairwise rounds)
    for (int s = 8; s > 0; s >>= 1) {
        __syncthreads();
        if (tt < s) {
            const int ba = (rr * 16 + tt) * KK;
            const int bb = (rr * 16 + tt + s) * KK;
            unsigned long long out[KK];
            int pa = 0, pb = 0;
            #pragma unroll
            for (int q = 0; q < KK; q++) {
                const unsigned long long ka = sk[ba + pa];
                const unsigned long long kb = sk[bb + pb];
                if (ka <= kb) { out[q] = ka; pa++; }
                else          { out[q] = kb; pb++; }
            }
            #pragma unroll
            for (int q = 0; q < KK; q++) sk[ba + q] = out[q];
        }
    }
    __syncthreads();
    knn[row_g * KK + tt] = (int)(sk[(rr * 16) * KK + tt] & 0xFFFFFFFFu);
}

__global__ void concat_k(const float* __restrict__ a, const float* __restrict__ b,
                         float* __restrict__ out)
{
    const int i = blockIdx.x, c = threadIdx.x;
    out[(size_t)i * 256 + c] = (c < DD) ? a[i * DD + c] : b[i * DD + c - DD];
}

// ---------------- host orchestration ---------------------------------------
static inline void gemm(const float* A, const float* B, const float* bias, float* C,
                        int M, int K, int N, int mode, const void* ei = nullptr)
{
    if ((N % TBN) == 0 && (M % TBM) == 0) {
        dim3 g(N / TBN, M / TBM);
        mma3_gemm_k<<<g, 256, MMA3_SMEM_BYTES>>>(A, B, bias, C, M, K, N, mode, ei);
    } else {
        dim3 g(N / GBN, M / GBM);
        gemm_k<<<g, 256>>>(A, B, bias, C, M, K, N, mode);
    }
}

extern "C" void kernel_launch(void* const* d_in, const int* in_sizes, int n_in,
                              void* d_out, int out_size)
{
    const float* x    = (const float*)d_in[0];
    const float* ea_i = (const float*)d_in[1];
    const float* sW1  = (const float*)d_in[2];
    const float* sb1  = (const float*)d_in[3];
    const float* sW2  = (const float*)d_in[4];
    const float* sb2  = (const float*)d_in[5];
    const float* uW1  = (const float*)d_in[6];
    const float* ub1  = (const float*)d_in[7];
    const float* uW2  = (const float*)d_in[8];
    const float* ub2  = (const float*)d_in[9];
    const float* rW   = (const float*)d_in[10];
    const float* rb   = (const float*)d_in[11];
    const float* dW1  = (const float*)d_in[12];
    const float* db1  = (const float*)d_in[13];
    const float* dW2  = (const float*)d_in[14];
    const float* db2  = (const float*)d_in[15];
    const float* dUW1 = (const float*)d_in[16];
    const float* dUb1 = (const float*)d_in[17];
    const float* dUW2 = (const float*)d_in[18];
    const float* dUb2 = (const float*)d_in[19];
    const float* fW1  = (const float*)d_in[20];
    const float* fb1  = (const float*)d_in[21];
    const float* fW2  = (const float*)d_in[22];
    const float* fb2  = (const float*)d_in[23];
    const void*  ei   = d_in[24];

    cudaFuncSetAttribute(mma3_gemm_k, cudaFuncAttributeMaxDynamicSharedMemorySize,
                         MMA3_SMEM_BYTES);
    cudaFuncSetAttribute(dist_sym_k, cudaFuncAttributeMaxDynamicSharedMemorySize,
                         MMA3_SMEM_BYTES);

    float *msg, *hid, *ea0, *ea1, *xs0, *xs1, *xd0, *xd1;
    float *agg, *tmpN, *P2, *cat, *sq, *xT, *dist, *zero;
    int   *knn;
    cudaGetSymbolAddress((void**)&msg,  g_msg);
    cudaGetSymbolAddress((void**)&hid,  g_hid);
    cudaGetSymbolAddress((void**)&ea0,  g_ea0);
    cudaGetSymbolAddress((void**)&ea1,  g_ea1);
    cudaGetSymbolAddress((void**)&xs0,  g_xs0);
    cudaGetSymbolAddress((void**)&xs1,  g_xs1);
    cudaGetSymbolAddress((void**)&xd0,  g_xd0);
    cudaGetSymbolAddress((void**)&xd1,  g_xd1);
    cudaGetSymbolAddress((void**)&agg,  g_agg);
    cudaGetSymbolAddress((void**)&tmpN, g_tmpN);
    cudaGetSymbolAddress((void**)&P2,   g_P2);
    cudaGetSymbolAddress((void**)&cat,  g_cat);
    cudaGetSymbolAddress((void**)&sq,   g_sq);
    cudaGetSymbolAddress((void**)&xT,   g_xT);
    cudaGetSymbolAddress((void**)&dist, g_dist);
    cudaGetSymbolAddress((void**)&zero, g_zero);
    cudaGetSymbolAddress((void**)&knn,  g_knn);

    detect_ei_k<<<1, 1>>>(ei);

    // ---------------- static branch: 3 conv layers + 2 edge refiners --------
    const float* xs_in = x;
    const float* ea_in = ea_i;
    float* xs_bufs[2] = { xs0, xs1 };
    float* ea_bufs[2] = { ea0, ea1 };
    for (int i = 0; i < 3; i++) {
        const float* W1 = sW1 + (size_t)i * 192 * HH;
        gemm(ea_in, W1, sb1 + i * HH, hid, NE, DE, HH, 2);              // eW + b1
        gemm(xs_in, W1 + (size_t)DE * HH, zero, tmpN, NN, DD, HH, 2);   // P = xs@W_x
        static_fuse_k<<<NE / 4, 256>>>(hid, tmpN, ei, msg);
        cudaMemsetAsync(agg, 0, (size_t)NN * DD * sizeof(float));
        gemm(msg, sW2 + (size_t)i * HH * DD, sb2 + i * DD, agg, NE, HH, DD, 3, ei);
        gemm(agg,  uW1 + (size_t)i * DD * HH, ub1 + i * HH, tmpN, NN, DD, HH, 0);
        float* xs_out = xs_bufs[i & 1];
        gemm(tmpN, uW2 + (size_t)i * HH * DD, ub2 + i * DD, xs_out, NN, HH, DD, 0);
        if (i < 2) {
            float* ea_out = ea_bufs[i & 1];
            gemm(ea_in, rW + (size_t)i * DE * DE, rb + i * DE, ea_out, NE, DE, DE, 0);
            ea_in = ea_out;
        }
        xs_in = xs_out;
    }

    // ---------------- dynamic branch: 2 kNN conv layers ---------------------
    const float* xd_in = x;
    float* xd_bufs[2] = { xd0, xd1 };
    for (int i = 0; i < 2; i++) {
        rownorm_k<<<NN / 8, 256>>>(xd_in, sq);
        transpose_k<<<dim3(NN / 32, DD / 32), dim3(32, 8)>>>(xd_in, xT);
        dist_sym_k<<<dim3(NN / TBM, NN / TBM), 256, MMA3_SMEM_BYTES>>>(xd_in, xT, sq, dist);
        topk_k<<<NN / 16, 256>>>(dist, knn);
        const float* W1 = dW1 + (size_t)i * 2 * DD * HH;
        gemm(xd_in, W1, zero, tmpN, NN, DD, HH, 2);                     // P1 = xd@W_top
        gemm(xd_in, W1 + (size_t)DD * HH, zero, P2, NN, DD, HH, 2);     // P2 = xd@W_bot
        dyn_fuse_k<<<NE / 4, 256>>>(tmpN, P2, knn, db1 + i * HH, msg);
        cudaMemsetAsync(agg, 0, (size_t)NN * DD * sizeof(float));
        gemm(msg, dW2 + (size_t)i * HH * DD, db2 + i * DD, agg, NE, HH, DD, 4);
        gemm(agg,  dUW1 + (size_t)i * DD * HH, dUb1 + i * HH, tmpN, NN, DD, HH, 0);
        float* xd_out = xd_bufs[i];
        gemm(tmpN, dUW2 + (size_t)i * HH * DD, dUb2 + i * DD, xd_out, NN, HH, DD, 0);
        xd_in = xd_out;
    }

    // ---------------- fuse ---------------------------------------------------
    concat_k<<<NN, 256>>>(xs_in, xd_in, cat);
    gemm(cat,  fW1, fb1, tmpN, NN, 2 * DD, HH, 0);
    gemm(tmpN, fW2, fb2, (float*)d_out, NN, HH, DD, 0);
}

// round 12
// speedup vs baseline: 2.0099x; 2.0099x over previous
#include <cuda_runtime.h>
#include <cstdint>
#include <cstddef>

// ---------------- problem constants (fixed by the dataset) ----------------
#define NN   16384      // nodes
#define NE   262144     // static edges (== NN * 16, also dynamic edge count)
#define DD   128        // node dim
#define DE   64         // edge dim
#define HH   256        // hidden
#define KK   16         // kNN

// ---------------- device scratch (allocation-free rule: __device__ globals) ----
__device__ float g_msg [(size_t)NE * 256];
__device__ float g_hid [(size_t)NE * 256];
__device__ float g_ea0 [(size_t)NE * DE];
__device__ float g_ea1 [(size_t)NE * DE];
__device__ float g_xs0 [NN * DD];
__device__ float g_xs1 [NN * DD];
__device__ float g_xd0 [NN * DD];
__device__ float g_xd1 [NN * DD];
__device__ float g_agg [NN * DD];
__device__ float g_tmpN[NN * HH];
__device__ float g_P2  [NN * HH];
__device__ float g_cat [NN * 2 * DD];
__device__ float g_sq  [NN];
__device__ float g_xT  [(size_t)DD * NN];
__device__ float g_dist[(size_t)NN * NN];
__device__ int   g_knn [NN * KK];
__device__ float g_zero[HH];          // zero-initialized bias
__device__ int   g_ei64flag;

// ---------------- edge_index dtype handling (int64 vs silently-int32) -----
__global__ void detect_ei_k(const void* p) {
    const unsigned long long* q = (const unsigned long long*)p;
    int ok = 1;
    #pragma unroll
    for (int i = 0; i < 8; i++)
        if (q[i] >= (unsigned long long)NN) ok = 0;
    g_ei64flag = ok;
}

__device__ __forceinline__ long long load_ei(const void* p, long long idx) {
    if (g_ei64flag) return ((const long long*)p)[idx];
    return (long long)((const int*)p)[idx];
}

// ---------------- tf32 helpers ----------------------------------------------
__device__ __forceinline__ float f2tf(float x) {
    uint32_t u;
    asm("cvt.rna.tf32.f32 %0, %1;" : "=r"(u) : "f"(x));
    return __uint_as_float(u);
}

#define MMA_TF32(acc, a0, a1, a2, a3, b0, b1)                                  \
    asm volatile(                                                              \
        "mma.sync.aligned.m16n8k8.row.col.f32.tf32.tf32.f32 "                  \
        "{%0,%1,%2,%3}, {%4,%5,%6,%7}, {%8,%9}, {%0,%1,%2,%3};"                \
        : "+f"(acc[0]), "+f"(acc[1]), "+f"(acc[2]), "+f"(acc[3])               \
        : "r"(a0), "r"(a1), "r"(a2), "r"(a3), "r"(b0), "r"(b1))

#define TBM 128
#define TBN 128
#define TBK 32
#define ASTR 36
#define BSTR 136
#define A_SZ (TBM * ASTR)
#define B_SZ (TBK * BSTR)
#define MMA3_SMEM_BYTES ((2 * A_SZ + 2 * B_SZ) * 4)   // 71680 B

// ---------------- 3xTF32 tensor-core GEMM (fp32-accurate) --------------------
// mode 0: relu(acc+bias) store; mode 2: acc+bias store
// mode 3: relu(acc+bias) atomicAdd into C[ei[NE+row]*N + col]
// mode 4: relu(acc+bias) atomicAdd into C[(row>>4)*N + col]
__global__ __launch_bounds__(256, 2) void mma3_gemm_k(
    const float* __restrict__ A, const float* __restrict__ B,
    const float* __restrict__ bias, float* __restrict__ C,
    int M, int K, int N, int mode, const void* __restrict__ ei)
{
    extern __shared__ float sm[];
    float* Ah = sm;
    float* Al = sm + A_SZ;
    float* Bh = sm + 2 * A_SZ;
    float* Bl = sm + 2 * A_SZ + B_SZ;

    const int tid  = threadIdx.x;
    const int lane = tid & 31;
    const int warp = tid >> 5;
    const int warp_m = warp & 1;
    const int warp_n = warp >> 1;
    const int row0 = blockIdx.y * TBM;
    const int col0 = blockIdx.x * TBN;
    const int g  = lane >> 2;
    const int tg = lane & 3;

    const int ar_ = tid >> 3, ac4 = tid & 7;
    const int bkr = tid >> 5, bc4 = tid & 31;

    float acc[4][4][4];
    #pragma unroll
    for (int mm = 0; mm < 4; mm++)
        #pragma unroll
        for (int nn = 0; nn < 4; nn++)
            #pragma unroll
            for (int r = 0; r < 4; r++) acc[mm][nn][r] = 0.f;

    const int ktiles = K / TBK;

    float4 pa[4], pb[4];
    #pragma unroll
    for (int p = 0; p < 4; p++)
        pa[p] = *(const float4*)(A + (size_t)(row0 + ar_ + 32 * p) * K + ac4 * 4);
    #pragma unroll
    for (int p = 0; p < 4; p++)
        pb[p] = *(const float4*)(B + (size_t)(bkr + 8 * p) * N + col0 + bc4 * 4);

    for (int kt = 0; kt < ktiles; kt++) {
        #pragma unroll
        for (int p = 0; p < 4; p++) {
            const float4 v = pa[p];
            float4 vh, vl;
            vh.x = f2tf(v.x); vl.x = f2tf(v.x - vh.x);
            vh.y = f2tf(v.y); vl.y = f2tf(v.y - vh.y);
            vh.z = f2tf(v.z); vl.z = f2tf(v.z - vh.z);
            vh.w = f2tf(v.w); vl.w = f2tf(v.w - vh.w);
            *(float4*)&Ah[(ar_ + 32 * p) * ASTR + ac4 * 4] = vh;
            *(float4*)&Al[(ar_ + 32 * p) * ASTR + ac4 * 4] = vl;
        }
        #pragma unroll
        for (int p = 0; p < 4; p++) {
            const float4 v = pb[p];
            float4 vh, vl;
            vh.x = f2tf(v.x); vl.x = f2tf(v.x - vh.x);
            vh.y = f2tf(v.y); vl.y = f2tf(v.y - vh.y);
            vh.z = f2tf(v.z); vl.z = f2tf(v.z - vh.z);
            vh.w = f2tf(v.w); vl.w = f2tf(v.w - vh.w);
            *(float4*)&Bh[(bkr + 8 * p) * BSTR + bc4 * 4] = vh;
            *(float4*)&Bl[(bkr + 8 * p) * BSTR + bc4 * 4] = vl;
        }
        __syncthreads();

        if (kt + 1 < ktiles) {
            const int ko = (kt + 1) * TBK;
            #pragma unroll
            for (int p = 0; p < 4; p++)
                pa[p] = *(const float4*)(A + (size_t)(row0 + ar_ + 32 * p) * K + ko + ac4 * 4);
            #pragma unroll
            for (int p = 0; p < 4; p++)
                pb[p] = *(const float4*)(B + (size_t)(ko + bkr + 8 * p) * N + col0 + bc4 * 4);
        }

        #pragma unroll
        for (int kk = 0; kk < 4; kk++) {
            const int kb = kk * 8;
            uint32_t af[4][4], bf[4][2];

            #pragma unroll
            for (int mm = 0; mm < 4; mm++) {
                const int ar = warp_m * 64 + mm * 16 + g;
                af[mm][0] = __float_as_uint(Ah[ar * ASTR + kb + tg]);
                af[mm][1] = __float_as_uint(Ah[(ar + 8) * ASTR + kb + tg]);
                af[mm][2] = __float_as_uint(Ah[ar * ASTR + kb + tg + 4]);
                af[mm][3] = __float_as_uint(Ah[(ar + 8) * ASTR + kb + tg + 4]);
            }
            #pragma unroll
            for (int nn = 0; nn < 4; nn++) {
                const int bc = warp_n * 32 + nn * 8 + g;
                bf[nn][0] = __float_as_uint(Bl[(kb + tg) * BSTR + bc]);
                bf[nn][1] = __float_as_uint(Bl[(kb + tg + 4) * BSTR + bc]);
            }
            #pragma unroll
            for (int mm = 0; mm < 4; mm++)
                #pragma unroll
                for (int nn = 0; nn < 4; nn++)
                    MMA_TF32(acc[mm][nn], af[mm][0], af[mm][1], af[mm][2], af[mm][3],
                             bf[nn][0], bf[nn][1]);
            #pragma unroll
            for (int nn = 0; nn < 4; nn++) {
                const int bc = warp_n * 32 + nn * 8 + g;
                bf[nn][0] = __float_as_uint(Bh[(kb + tg) * BSTR + bc]);
                bf[nn][1] = __float_as_uint(Bh[(kb + tg + 4) * BSTR + bc]);
            }
            #pragma unroll
            for (int mm = 0; mm < 4; mm++)
                #pragma unroll
                for (int nn = 0; nn < 4; nn++)
                    MMA_TF32(acc[mm][nn], af[mm][0], af[mm][1], af[mm][2], af[mm][3],
                             bf[nn][0], bf[nn][1]);
            #pragma unroll
            for (int mm = 0; mm < 4; mm++) {
                const int ar = warp_m * 64 + mm * 16 + g;
                af[mm][0] = __float_as_uint(Al[ar * ASTR + kb + tg]);
                af[mm][1] = __float_as_uint(Al[(ar + 8) * ASTR + kb + tg]);
                af[mm][2] = __float_as_uint(Al[ar * ASTR + kb + tg + 4]);
                af[mm][3] = __float_as_uint(Al[(ar + 8) * ASTR + kb + tg + 4]);
            }
            #pragma unroll
            for (int mm = 0; mm < 4; mm++)
                #pragma unroll
                for (int nn = 0; nn < 4; nn++)
                    MMA_TF32(acc[mm][nn], af[mm][0], af[mm][1], af[mm][2], af[mm][3],
                             bf[nn][0], bf[nn][1]);
        }
        __syncthreads();
    }

    if (mode <= 2) {
        #pragma unroll
        for (int nn = 0; nn < 4; nn++) {
            const int col = col0 + warp_n * 32 + nn * 8 + tg * 2;
            const float bv0 = bias[col], bv1 = bias[col + 1];
            #pragma unroll
            for (int mm = 0; mm < 4; mm++) {
                const int row = row0 + warp_m * 64 + mm * 16 + g;
                float2 o0, o1;
                if (mode == 0) {
                    o0.x = fmaxf(acc[mm][nn][0] + bv0, 0.f);
                    o0.y = fmaxf(acc[mm][nn][1] + bv1, 0.f);
                    o1.x = fmaxf(acc[mm][nn][2] + bv0, 0.f);
                    o1.y = fmaxf(acc[mm][nn][3] + bv1, 0.f);
                } else {
                    o0.x = acc[mm][nn][0] + bv0;
                    o0.y = acc[mm][nn][1] + bv1;
                    o1.x = acc[mm][nn][2] + bv0;
                    o1.y = acc[mm][nn][3] + bv1;
                }
                *(float2*)(C + (size_t)row * N + col)       = o0;
                *(float2*)(C + (size_t)(row + 8) * N + col) = o1;
            }
        }
    } else {
        #pragma unroll
        for (int mm = 0; mm < 4; mm++) {
            const int row = row0 + warp_m * 64 + mm * 16 + g;
            long long d0, d1;
            if (mode == 3) {
                d0 = load_ei(ei, (long long)NE + row);
                d1 = load_ei(ei, (long long)NE + row + 8);
            } else {
                d0 = row >> 4;
                d1 = (row + 8) >> 4;
            }
            #pragma unroll
            for (int nn = 0; nn < 4; nn++) {
                const int col = col0 + warp_n * 32 + nn * 8 + tg * 2;
                const float bv0 = bias[col], bv1 = bias[col + 1];
                atomicAdd(&C[d0 * N + col],     fmaxf(acc[mm][nn][0] + bv0, 0.f));
                atomicAdd(&C[d0 * N + col + 1], fmaxf(acc[mm][nn][1] + bv1, 0.f));
                atomicAdd(&C[d1 * N + col],     fmaxf(acc[mm][nn][2] + bv0, 0.f));
                atomicAdd(&C[d1 * N + col + 1], fmaxf(acc[mm][nn][3] + bv1, 0.f));
            }
        }
    }
}

// ---------------- symmetric distance GEMM (lower triangle + mirror) ----------
__global__ __launch_bounds__(256, 2) void dist_sym_k(
    const float* __restrict__ X, const float* __restrict__ XT,
    const float* __restrict__ sq, float* __restrict__ C)
{
    const int bi = blockIdx.y, bj = blockIdx.x;
    if (bj > bi) return;

    extern __shared__ float sm[];
    float* Ah = sm;
    float* Al = sm + A_SZ;
    float* Bh = sm + 2 * A_SZ;
    float* Bl = sm + 2 * A_SZ + B_SZ;

    const int tid  = threadIdx.x;
    const int lane = tid & 31;
    const int warp = tid >> 5;
    const int warp_m = warp & 1;
    const int warp_n = warp >> 1;
    const int row0 = bi * TBM;
    const int col0 = bj * TBM;
    const int g  = lane >> 2;
    const int tg = lane & 3;

    const int ar_ = tid >> 3, ac4 = tid & 7;
    const int bkr = tid >> 5, bc4 = tid & 31;

    float acc[4][4][4];
    #pragma unroll
    for (int mm = 0; mm < 4; mm++)
        #pragma unroll
        for (int nn = 0; nn < 4; nn++)
            #pragma unroll
            for (int r = 0; r < 4; r++) acc[mm][nn][r] = 0.f;

    float4 pa[4], pb[4];
    #pragma unroll
    for (int p = 0; p < 4; p++)
        pa[p] = *(const float4*)(X + (size_t)(row0 + ar_ + 32 * p) * DD + ac4 * 4);
    #pragma unroll
    for (int p = 0; p < 4; p++)
        pb[p] = *(const float4*)(XT + (size_t)(bkr + 8 * p) * NN + col0 + bc4 * 4);

    #pragma unroll
    for (int kt = 0; kt < DD / TBK; kt++) {
        #pragma unroll
        for (int p = 0; p < 4; p++) {
            const float4 v = pa[p];
            float4 vh, vl;
            vh.x = f2tf(v.x); vl.x = f2tf(v.x - vh.x);
            vh.y = f2tf(v.y); vl.y = f2tf(v.y - vh.y);
            vh.z = f2tf(v.z); vl.z = f2tf(v.z - vh.z);
            vh.w = f2tf(v.w); vl.w = f2tf(v.w - vh.w);
            *(float4*)&Ah[(ar_ + 32 * p) * ASTR + ac4 * 4] = vh;
            *(float4*)&Al[(ar_ + 32 * p) * ASTR + ac4 * 4] = vl;
        }
        #pragma unroll
        for (int p = 0; p < 4; p++) {
            const float4 v = pb[p];
            float4 vh, vl;
            vh.x = f2tf(v.x); vl.x = f2tf(v.x - vh.x);
            vh.y = f2tf(v.y); vl.y = f2tf(v.y - vh.y);
            vh.z = f2tf(v.z); vl.z = f2tf(v.z - vh.z);
            vh.w = f2tf(v.w); vl.w = f2tf(v.w - vh.w);
            *(float4*)&Bh[(bkr + 8 * p) * BSTR + bc4 * 4] = vh;
            *(float4*)&Bl[(bkr + 8 * p) * BSTR + bc4 * 4] = vl;
        }
        __syncthreads();

        if (kt + 1 < DD / TBK) {
            const int ko = (kt + 1) * TBK;
            #pragma unroll
            for (int p = 0; p < 4; p++)
                pa[p] = *(const float4*)(X + (size_t)(row0 + ar_ + 32 * p) * DD + ko + ac4 * 4);
            #pragma unroll
            for (int p = 0; p < 4; p++)
                pb[p] = *(const float4*)(XT + (size_t)(ko + bkr + 8 * p) * NN + col0 + bc4 * 4);
        }

        #pragma unroll
        for (int kk = 0; kk < 4; kk++) {
            const int kb = kk * 8;
            uint32_t af[4][4], bf[4][2];

            #pragma unroll
            for (int mm = 0; mm < 4; mm++) {
                const int ar = warp_m * 64 + mm * 16 + g;
                af[mm][0] = __float_as_uint(Ah[ar * ASTR + kb + tg]);
                af[mm][1] = __float_as_uint(Ah[(ar + 8) * ASTR + kb + tg]);
                af[mm][2] = __float_as_uint(Ah[ar * ASTR + kb + tg + 4]);
                af[mm][3] = __float_as_uint(Ah[(ar + 8) * ASTR + kb + tg + 4]);
            }
            #pragma unroll
            for (int nn = 0; nn < 4; nn++) {
                const int bc = warp_n * 32 + nn * 8 + g;
                bf[nn][0] = __float_as_uint(Bl[(kb + tg) * BSTR + bc]);
                bf[nn][1] = __float_as_uint(Bl[(kb + tg + 4) * BSTR + bc]);
            }
            #pragma unroll
            for (int mm = 0; mm < 4; mm++)
                #pragma unroll
                for (int nn = 0; nn < 4; nn++)
                    MMA_TF32(acc[mm][nn], af[mm][0], af[mm][1], af[mm][2], af[mm][3],
                             bf[nn][0], bf[nn][1]);
            #pragma unroll
            for (int nn = 0; nn < 4; nn++) {
                const int bc = warp_n * 32 + nn * 8 + g;
                bf[nn][0] = __float_as_uint(Bh[(kb + tg) * BSTR + bc]);
                bf[nn][1] = __float_as_uint(Bh[(kb + tg + 4) * BSTR + bc]);
            }
            #pragma unroll
            for (int mm = 0; mm < 4; mm++)
                #pragma unroll
                for (int nn = 0; nn < 4; nn++)
                    MMA_TF32(acc[mm][nn], af[mm][0], af[mm][1], af[mm][2], af[mm][3],
                             bf[nn][0], bf[nn][1]);
            #pragma unroll
            for (int mm = 0; mm < 4; mm++) {
                const int ar = warp_m * 64 + mm * 16 + g;
                af[mm][0] = __float_as_uint(Al[ar * ASTR + kb + tg]);
                af[mm][1] = __float_as_uint(Al[(ar + 8) * ASTR + kb + tg]);
                af[mm][2] = __float_as_uint(Al[ar * ASTR + kb + tg + 4]);
                af[mm][3] = __float_as_uint(Al[(ar + 8) * ASTR + kb + tg + 4]);
            }
            #pragma unroll
            for (int mm = 0; mm < 4; mm++)
                #pragma unroll
                for (int nn = 0; nn < 4; nn++)
                    MMA_TF32(acc[mm][nn], af[mm][0], af[mm][1], af[mm][2], af[mm][3],
                             bf[nn][0], bf[nn][1]);
        }
        __syncthreads();
    }

    #pragma unroll
    for (int nn = 0; nn < 4; nn++) {
        const int col = col0 + warp_n * 32 + nn * 8 + tg * 2;
        const float bv0 = sq[col], bv1 = sq[col + 1];
        #pragma unroll
        for (int mm = 0; mm < 4; mm++) {
            const int row = row0 + warp_m * 64 + mm * 16 + g;
            float2 o0, o1;
            o0.x = bv0 - 2.f * acc[mm][nn][0];
            o0.y = bv1 - 2.f * acc[mm][nn][1];
            o1.x = bv0 - 2.f * acc[mm][nn][2];
            o1.y = bv1 - 2.f * acc[mm][nn][3];
            *(float2*)(C + (size_t)row * NN + col)       = o0;
            *(float2*)(C + (size_t)(row + 8) * NN + col) = o1;
        }
    }

    if (bi != bj) {
        float* Sc = sm;
        #pragma unroll
        for (int mm = 0; mm < 4; mm++) {
            const int lr = warp_m * 64 + mm * 16 + g;
            const float s0 = sq[row0 + lr], s1 = sq[row0 + lr + 8];
            #pragma unroll
            for (int nn = 0; nn < 4; nn++) {
                const int lc = warp_n * 32 + nn * 8 + tg * 2;
                Sc[lc * 132 + lr]            = s0 - 2.f * acc[mm][nn][0];
                Sc[(lc + 1) * 132 + lr]      = s0 - 2.f * acc[mm][nn][1];
                Sc[lc * 132 + lr + 8]        = s1 - 2.f * acc[mm][nn][2];
                Sc[(lc + 1) * 132 + lr + 8]  = s1 - 2.f * acc[mm][nn][3];
            }
        }
        __syncthreads();
        #pragma unroll
        for (int it = 0; it < 16; it++) {
            const int lc = warp + it * 8;
            const float4 v = *(const float4*)&Sc[lc * 132 + lane * 4];
            *(float4*)(C + (size_t)(col0 + lc) * NN + row0 + lane * 4) = v;
        }
    }
}

// ---------------- fallback SIMT GEMM (used only when N % 128 != 0) ----------
#define GBM 128
#define GBN 64
#define GBK 32

__global__ __launch_bounds__(256, 2) void gemm_k(
    const float* __restrict__ A, const float* __restrict__ B,
    const float* __restrict__ bias, float* __restrict__ C,
    int M, int K, int N, int mode)
{
    __shared__ float As[GBK][GBM + 4];
    __shared__ float Bs[GBK][GBN];
    const int tid  = threadIdx.x;
    const int row0 = blockIdx.y * GBM;
    const int col0 = blockIdx.x * GBN;
    const int tr = tid >> 4;
    const int tc = tid & 15;

    float acc[8][4];
    #pragma unroll
    for (int i = 0; i < 8; i++)
        #pragma unroll
        for (int j = 0; j < 4; j++) acc[i][j] = 0.f;

    const int ktiles = K / GBK;
    for (int kt = 0; kt < ktiles; kt++) {
        #pragma unroll
        for (int p = 0; p < 4; p++) {
            int lin = tid + 256 * p;
            int r = lin >> 3, q = lin & 7;
            const float4 v = *(const float4*)(A + (size_t)(row0 + r) * K + kt * GBK + q * 4);
            As[q * 4 + 0][r] = v.x; As[q * 4 + 1][r] = v.y;
            As[q * 4 + 2][r] = v.z; As[q * 4 + 3][r] = v.w;
        }
        #pragma unroll
        for (int p = 0; p < 2; p++) {
            int lin = tid + 256 * p;
            int kr = lin >> 4, j4 = lin & 15;
            *(float4*)&Bs[kr][j4 * 4] =
                *(const float4*)(B + (size_t)(kt * GBK + kr) * N + col0 + j4 * 4);
        }
        __syncthreads();
        #pragma unroll
        for (int k = 0; k < GBK; k++) {
            float a[8], b[4];
            *(float4*)&a[0] = *(const float4*)&As[k][tr * 8];
            *(float4*)&a[4] = *(const float4*)&As[k][tr * 8 + 4];
            *(float4*)&b[0] = *(const float4*)&Bs[k][tc * 4];
            #pragma unroll
            for (int i = 0; i < 8; i++)
                #pragma unroll
                for (int j = 0; j < 4; j++)
                    acc[i][j] = fmaf(a[i], b[j], acc[i][j]);
        }
        __syncthreads();
    }

    float bv[4];
    #pragma unroll
    for (int j = 0; j < 4; j++) bv[j] = bias[col0 + tc * 4 + j];

    #pragma unroll
    for (int i = 0; i < 8; i++) {
        const int row = row0 + tr * 8 + i;
        float4 o;
        o.x = fmaxf(acc[i][0] + bv[0], 0.f);
        o.y = fmaxf(acc[i][1] + bv[1], 0.f);
        o.z = fmaxf(acc[i][2] + bv[2], 0.f);
        o.w = fmaxf(acc[i][3] + bv[3], 0.f);
        *(float4*)(C + (size_t)row * N + col0 + tc * 4) = o;
    }
}

// ---------------- fusion kernels (factored first MLP layer) ------------------
__global__ __launch_bounds__(256) void static_fuse_k(
    const float* __restrict__ eW, const float* __restrict__ P,
    const void* __restrict__ ei, float* __restrict__ hid)
{
    const int e  = blockIdx.x * 4 + (threadIdx.x >> 6);
    const int c4 = threadIdx.x & 63;
    const long long s = load_ei(ei, e);
    const long long d = load_ei(ei, (long long)NE + e);
    const float4 a = *(const float4*)(eW + (size_t)e * HH + c4 * 4);
    const float4 ps = *(const float4*)(P + (size_t)s * HH + c4 * 4);
    const float4 pd = *(const float4*)(P + (size_t)d * HH + c4 * 4);
    float4 o;
    o.x = fmaxf(a.x + ps.x - pd.x, 0.f);
    o.y = fmaxf(a.y + ps.y - pd.y, 0.f);
    o.z = fmaxf(a.z + ps.z - pd.z, 0.f);
    o.w = fmaxf(a.w + ps.w - pd.w, 0.f);
    *(float4*)(hid + (size_t)e * HH + c4 * 4) = o;
}

__global__ __launch_bounds__(256) void dyn_fuse_k(
    const float* __restrict__ P1, const float* __restrict__ P2,
    const int* __restrict__ knn, const float* __restrict__ bias,
    float* __restrict__ hid)
{
    const int e  = blockIdx.x * 4 + (threadIdx.x >> 6);
    const int c4 = threadIdx.x & 63;
    const int i = e >> 4;
    const int j = knn[e];
    const float4 p1 = *(const float4*)(P1 + (size_t)i * HH + c4 * 4);
    const float4 pi = *(const float4*)(P2 + (size_t)i * HH + c4 * 4);
    const float4 pj = *(const float4*)(P2 + (size_t)j * HH + c4 * 4);
    const float4 b  = *(const float4*)(bias + c4 * 4);
    float4 o;
    o.x = fmaxf(p1.x - pi.x + pj.x + b.x, 0.f);
    o.y = fmaxf(p1.y - pi.y + pj.y + b.y, 0.f);
    o.z = fmaxf(p1.z - pi.z + pj.z + b.z, 0.f);
    o.w = fmaxf(p1.w - pi.w + pj.w + b.w, 0.f);
    *(float4*)(hid + (size_t)e * HH + c4 * 4) = o;
}

// ---------------- small helper kernels --------------------------------------
__global__ void rownorm_k(const float* __restrict__ x, float* __restrict__ sq)
{
    const int row  = blockIdx.x * 8 + (threadIdx.x >> 5);
    const int lane = threadIdx.x & 31;
    const float* p = x + (size_t)row * DD;
    float s = 0.f;
    #pragma unroll
    for (int q = 0; q < 4; q++) { float v = p[lane + 32 * q]; s = fmaf(v, v, s); }
    #pragma unroll
    for (int o = 16; o > 0; o >>= 1) s += __shfl_xor_sync(0xffffffffu, s, o);
    if (lane == 0) sq[row] = s;
}

__global__ void transpose_k(const float* __restrict__ in, float* __restrict__ out)
{
    __shared__ float t[32][33];
    const int j0 = blockIdx.x * 32, k0 = blockIdx.y * 32;
    for (int r = threadIdx.y; r < 32; r += 8)
        t[r][threadIdx.x] = in[(size_t)(j0 + r) * DD + k0 + threadIdx.x];
    __syncthreads();
    for (int r = threadIdx.y; r < 32; r += 8)
        out[(size_t)(k0 + r) * NN + j0 + threadIdx.x] = t[threadIdx.x][r];
}

// ---------------- top-16: u64 keys, SLOT-MAJOR smem queues -------------------
// 16 rows per 256-thread block; 16 threads per row, each scanning 1024 elems.
// key = ordered_u32(val) << 32 | col  -> one u64 compare = (val, idx) order.
// Sentinel = key(+inf, idx 0xFFFFFFFF) (decodes to +inf, never NaN).
// Queue layout is SLOT-MAJOR: sk[slot * 256 + tid].  Bank of any access is
// (tid*2) mod 32 -- independent of slot -- so divergent insertion loops are
// conflict-free (the R11 thread-major layout put every queue on bank 0).
__global__ __launch_bounds__(256) void topk_k(const float* __restrict__ dist,
                                              int* __restrict__ knn)
{
    __shared__ unsigned long long sk[KK * 256];   // 32 KB, slot-major
    const unsigned long long SENT = 0xFF800000FFFFFFFFull;  // (+inf, idxmax)
    const int tid = threadIdx.x;
    const int rr  = tid >> 4;          // row within block
    const int tt  = tid & 15;          // thread within row
    const int row_g = blockIdx.x * 16 + rr;
    const float* row = dist + (size_t)row_g * NN;

    #pragma unroll
    for (int q = 0; q < KK; q++) sk[q * 256 + tid] = SENT;
    unsigned long long worst_key = SENT;
    float worstf = __int_as_float(0x7f800000);   // +inf

    for (int c = 0; c < NN / 64; c++) {
        const float4 v = *(const float4*)(row + c * 64 + tt * 4);
        const float mn = fminf(fminf(v.x, v.y), fminf(v.z, v.w));
        if (mn <= worstf) {
            const int j0 = c * 64 + tt * 4;
            const float vv[4] = { v.x, v.y, v.z, v.w };
            #pragma unroll
            for (int u = 0; u < 4; u++) {
                uint32_t ou = __float_as_uint(vv[u]);
                ou = (ou & 0x80000000u) ? ~ou : (ou | 0x80000000u);
                const unsigned long long key =
                    ((unsigned long long)ou << 32) | (uint32_t)(j0 + u);
                if (key < worst_key) {
                    int p = KK - 1;
                    while (p > 0 && sk[(p - 1) * 256 + tid] > key) {
                        sk[p * 256 + tid] = sk[(p - 1) * 256 + tid];
                        p--;
                    }
                    sk[p * 256 + tid] = key;
                    worst_key = sk[(KK - 1) * 256 + tid];
                    uint32_t wo = (uint32_t)(worst_key >> 32);
                    wo = (wo & 0x80000000u) ? (wo ^ 0x80000000u) : ~wo;
                    worstf = __uint_as_float(wo);
                }
            }
        }
    }

    // merge 16 sorted lists per row (4 pairwise rounds); list u of row rr
    // lives in thread-column (rr*16 + u), slot-major.
    for (int s = 8; s > 0; s >>= 1) {
        __syncthreads();
        if (tt < s) {
            const int ca = rr * 16 + tt;
            const int cb = rr * 16 + tt + s;
            unsigned long long out[KK];
            int pa = 0, pb = 0;
            #pragma unroll
            for (int q = 0; q < KK; q++) {
                const unsigned long long ka = sk[pa * 256 + ca];
                const unsigned long long kb = sk[pb * 256 + cb];
                if (ka <= kb) { out[q] = ka; pa++; }
                else          { out[q] = kb; pb++; }
            }
            #pragma unroll
            for (int q = 0; q < KK; q++) sk[q * 256 + ca] = out[q];
        }
    }
    __syncthreads();
    knn[row_g * KK + tt] = (int)(sk[tt * 256 + rr * 16] & 0xFFFFFFFFu);
}

__global__ void concat_k(const float* __restrict__ a, const float* __restrict__ b,
                         float* __restrict__ out)
{
    const int i = blockIdx.x, c = threadIdx.x;
    out[(size_t)i * 256 + c] = (c < DD) ? a[i * DD + c] : b[i * DD + c - DD];
}

// ---------------- host orchestration ---------------------------------------
static inline void gemm(const float* A, const float* B, const float* bias, float* C,
                        int M, int K, int N, int mode, const void* ei = nullptr)
{
    if ((N % TBN) == 0 && (M % TBM) == 0) {
        dim3 g(N / TBN, M / TBM);
        mma3_gemm_k<<<g, 256, MMA3_SMEM_BYTES>>>(A, B, bias, C, M, K, N, mode, ei);
    } else {
        dim3 g(N / GBN, M / GBM);
        gemm_k<<<g, 256>>>(A, B, bias, C, M, K, N, mode);
    }
}

extern "C" void kernel_launch(void* const* d_in, const int* in_sizes, int n_in,
                              void* d_out, int out_size)
{
    const float* x    = (const float*)d_in[0];
    const float* ea_i = (const float*)d_in[1];
    const float* sW1  = (const float*)d_in[2];
    const float* sb1  = (const float*)d_in[3];
    const float* sW2  = (const float*)d_in[4];
    const float* sb2  = (const float*)d_in[5];
    const float* uW1  = (const float*)d_in[6];
    const float* ub1  = (const float*)d_in[7];
    const float* uW2  = (const float*)d_in[8];
    const float* ub2  = (const float*)d_in[9];
    const float* rW   = (const float*)d_in[10];
    const float* rb   = (const float*)d_in[11];
    const float* dW1  = (const float*)d_in[12];
    const float* db1  = (const float*)d_in[13];
    const float* dW2  = (const float*)d_in[14];
    const float* db2  = (const float*)d_in[15];
    const float* dUW1 = (const float*)d_in[16];
    const float* dUb1 = (const float*)d_in[17];
    const float* dUW2 = (const float*)d_in[18];
    const float* dUb2 = (const float*)d_in[19];
    const float* fW1  = (const float*)d_in[20];
    const float* fb1  = (const float*)d_in[21];
    const float* fW2  = (const float*)d_in[22];
    const float* fb2  = (const float*)d_in[23];
    const void*  ei   = d_in[24];

    cudaFuncSetAttribute(mma3_gemm_k, cudaFuncAttributeMaxDynamicSharedMemorySize,
                         MMA3_SMEM_BYTES);
    cudaFuncSetAttribute(dist_sym_k, cudaFuncAttributeMaxDynamicSharedMemorySize,
                         MMA3_SMEM_BYTES);

    float *msg, *hid, *ea0, *ea1, *xs0, *xs1, *xd0, *xd1;
    float *agg, *tmpN, *P2, *cat, *sq, *xT, *dist, *zero;
    int   *knn;
    cudaGetSymbolAddress((void**)&msg,  g_msg);
    cudaGetSymbolAddress((void**)&hid,  g_hid);
    cudaGetSymbolAddress((void**)&ea0,  g_ea0);
    cudaGetSymbolAddress((void**)&ea1,  g_ea1);
    cudaGetSymbolAddress((void**)&xs0,  g_xs0);
    cudaGetSymbolAddress((void**)&xs1,  g_xs1);
    cudaGetSymbolAddress((void**)&xd0,  g_xd0);
    cudaGetSymbolAddress((void**)&xd1,  g_xd1);
    cudaGetSymbolAddress((void**)&agg,  g_agg);
    cudaGetSymbolAddress((void**)&tmpN, g_tmpN);
    cudaGetSymbolAddress((void**)&P2,   g_P2);
    cudaGetSymbolAddress((void**)&cat,  g_cat);
    cudaGetSymbolAddress((void**)&sq,   g_sq);
    cudaGetSymbolAddress((void**)&xT,   g_xT);
    cudaGetSymbolAddress((void**)&dist, g_dist);
    cudaGetSymbolAddress((void**)&zero, g_zero);
    cudaGetSymbolAddress((void**)&knn,  g_knn);

    detect_ei_k<<<1, 1>>>(ei);

    // ---------------- static branch: 3 conv layers + 2 edge refiners --------
    const float* xs_in = x;
    const float* ea_in = ea_i;
    float* xs_bufs[2] = { xs0, xs1 };
    float* ea_bufs[2] = { ea0, ea1 };
    for (int i = 0; i < 3; i++) {
        const float* W1 = sW1 + (size_t)i * 192 * HH;
        gemm(ea_in, W1, sb1 + i * HH, hid, NE, DE, HH, 2);              // eW + b1
        gemm(xs_in, W1 + (size_t)DE * HH, zero, tmpN, NN, DD, HH, 2);   // P = xs@W_x
        static_fuse_k<<<NE / 4, 256>>>(hid, tmpN, ei, msg);
        cudaMemsetAsync(agg, 0, (size_t)NN * DD * sizeof(float));
        gemm(msg, sW2 + (size_t)i * HH * DD, sb2 + i * DD, agg, NE, HH, DD, 3, ei);
        gemm(agg,  uW1 + (size_t)i * DD * HH, ub1 + i * HH, tmpN, NN, DD, HH, 0);
        float* xs_out = xs_bufs[i & 1];
        gemm(tmpN, uW2 + (size_t)i * HH * DD, ub2 + i * DD, xs_out, NN, HH, DD, 0);
        if (i < 2) {
            float* ea_out = ea_bufs[i & 1];
            gemm(ea_in, rW + (size_t)i * DE * DE, rb + i * DE, ea_out, NE, DE, DE, 0);
            ea_in = ea_out;
        }
        xs_in = xs_out;
    }

    // ---------------- dynamic branch: 2 kNN conv layers ---------------------
    const float* xd_in = x;
    float* xd_bufs[2] = { xd0, xd1 };
    for (int i = 0; i < 2; i++) {
        rownorm_k<<<NN / 8, 256>>>(xd_in, sq);
        transpose_k<<<dim3(NN / 32, DD / 32), dim3(32, 8)>>>(xd_in, xT);
        dist_sym_k<<<dim3(NN / TBM, NN / TBM), 256, MMA3_SMEM_BYTES>>>(xd_in, xT, sq, dist);
        topk_k<<<NN / 16, 256>>>(dist, knn);
        const float* W1 = dW1 + (size_t)i * 2 * DD * HH;
        gemm(xd_in, W1, zero, tmpN, NN, DD, HH, 2);                     // P1 = xd@W_top
        gemm(xd_in, W1 + (size_t)DD * HH, zero, P2, NN, DD, HH, 2);     // P2 = xd@W_bot
        dyn_fuse_k<<<NE / 4, 256>>>(tmpN, P2, knn, db1 + i * HH, msg);
        cudaMemsetAsync(agg, 0, (size_t)NN * DD * sizeof(float));
        gemm(msg, dW2 + (size_t)i * HH * DD, db2 + i * DD, agg, NE, HH, DD, 4);
        gemm(agg,  dUW1 + (size_t)i * DD * HH, dUb1 + i * HH, tmpN, NN, DD, HH, 0);
        float* xd_out = xd_bufs[i];
        gemm(tmpN, dUW2 + (size_t)i * HH * DD, dUb2 + i * DD, xd_out, NN, HH, DD, 0);
        xd_in = xd_out;
    }

    // ---------------- fuse ---------------------------------------------------
    concat_k<<<NN, 256>>>(xs_in, xd_in, cat);
    gemm(cat,  fW1, fb1, tmpN, NN, 2 * DD, HH, 0);
    gemm(tmpN, fW2, fb2, (float*)d_out, NN, HH, DD, 0);
}

// round 13
// speedup vs baseline: 2.0409x; 1.0154x over previous
#include <cuda_runtime.h>
#include <cstdint>
#include <cstddef>

// ---------------- problem constants (fixed by the dataset) ----------------
#define NN   16384      // nodes
#define NE   262144     // static edges (== NN * 16, also dynamic edge count)
#define DD   128        // node dim
#define DE   64         // edge dim
#define HH   256        // hidden
#define KK   16         // kNN

// ---------------- device scratch (allocation-free rule: __device__ globals) ----
__device__ float g_msg [(size_t)NE * 256];
__device__ float g_ea0 [(size_t)NE * DE];
__device__ float g_ea1 [(size_t)NE * DE];
__device__ float g_xs0 [NN * DD];
__device__ float g_xs1 [NN * DD];
__device__ float g_xd0 [NN * DD];
__device__ float g_xd1 [NN * DD];
__device__ float g_agg [NN * DD];
__device__ float g_tmpN[NN * HH];
__device__ float g_P2  [NN * HH];
__device__ float g_cat [NN * 2 * DD];
__device__ float g_sq  [NN];
__device__ float g_xT  [(size_t)DD * NN];
__device__ float g_dist[(size_t)NN * NN];
__device__ int   g_knn [NN * KK];
__device__ float g_zero[HH];          // zero-initialized bias
__device__ float g_Wd  [DD * HH];     // W_top - W_bot (dynamic layer scratch)
__device__ int   g_ei64flag;

// ---------------- edge_index dtype handling (int64 vs silently-int32) -----
__global__ void detect_ei_k(const void* p) {
    const unsigned long long* q = (const unsigned long long*)p;
    int ok = 1;
    #pragma unroll
    for (int i = 0; i < 8; i++)
        if (q[i] >= (unsigned long long)NN) ok = 0;
    g_ei64flag = ok;
}

__device__ __forceinline__ long long load_ei(const void* p, long long idx) {
    if (g_ei64flag) return ((const long long*)p)[idx];
    return (long long)((const int*)p)[idx];
}

// ---------------- tf32 helpers ----------------------------------------------
__device__ __forceinline__ float f2tf(float x) {
    uint32_t u;
    asm("cvt.rna.tf32.f32 %0, %1;" : "=r"(u) : "f"(x));
    return __uint_as_float(u);
}

#define MMA_TF32(acc, a0, a1, a2, a3, b0, b1)                                  \
    asm volatile(                                                              \
        "mma.sync.aligned.m16n8k8.row.col.f32.tf32.tf32.f32 "                  \
        "{%0,%1,%2,%3}, {%4,%5,%6,%7}, {%8,%9}, {%0,%1,%2,%3};"                \
        : "+f"(acc[0]), "+f"(acc[1]), "+f"(acc[2]), "+f"(acc[3])               \
        : "r"(a0), "r"(a1), "r"(a2), "r"(a3), "r"(b0), "r"(b1))

#define TBM 128
#define TBN 128
#define TBK 32
#define ASTR 36
#define BSTR 136
#define A_SZ (TBM * ASTR)
#define B_SZ (TBK * BSTR)
#define MMA3_SMEM_BYTES ((2 * A_SZ + 2 * B_SZ) * 4)   // 71680 B

// ---------------- 3xTF32 tensor-core GEMM (fp32-accurate) --------------------
// mode 0: relu(acc+bias) store; mode 2: acc+bias store
// mode 3: relu(acc+bias) atomicAdd into C[ei[NE+row]*N + col]
// mode 4: relu(acc+bias) atomicAdd into C[(row>>4)*N + col]
// mode 5: relu(acc+bias + P[ei[row]]*N+col - P[ei[NE+row]]*N+col) store
//         (static edge-fusion folded into the eW GEMM epilogue; N == HH)
__global__ __launch_bounds__(256, 2) void mma3_gemm_k(
    const float* __restrict__ A, const float* __restrict__ B,
    const float* __restrict__ bias, float* __restrict__ C,
    int M, int K, int N, int mode, const void* __restrict__ ei,
    const float* __restrict__ P)
{
    extern __shared__ float sm[];
    float* Ah = sm;
    float* Al = sm + A_SZ;
    float* Bh = sm + 2 * A_SZ;
    float* Bl = sm + 2 * A_SZ + B_SZ;

    const int tid  = threadIdx.x;
    const int lane = tid & 31;
    const int warp = tid >> 5;
    const int warp_m = warp & 1;
    const int warp_n = warp >> 1;
    const int row0 = blockIdx.y * TBM;
    const int col0 = blockIdx.x * TBN;
    const int g  = lane >> 2;
    const int tg = lane & 3;

    const int ar_ = tid >> 3, ac4 = tid & 7;
    const int bkr = tid >> 5, bc4 = tid & 31;

    float acc[4][4][4];
    #pragma unroll
    for (int mm = 0; mm < 4; mm++)
        #pragma unroll
        for (int nn = 0; nn < 4; nn++)
            #pragma unroll
            for (int r = 0; r < 4; r++) acc[mm][nn][r] = 0.f;

    const int ktiles = K / TBK;

    float4 pa[4], pb[4];
    #pragma unroll
    for (int p = 0; p < 4; p++)
        pa[p] = *(const float4*)(A + (size_t)(row0 + ar_ + 32 * p) * K + ac4 * 4);
    #pragma unroll
    for (int p = 0; p < 4; p++)
        pb[p] = *(const float4*)(B + (size_t)(bkr + 8 * p) * N + col0 + bc4 * 4);

    for (int kt = 0; kt < ktiles; kt++) {
        #pragma unroll
        for (int p = 0; p < 4; p++) {
            const float4 v = pa[p];
            float4 vh, vl;
            vh.x = f2tf(v.x); vl.x = f2tf(v.x - vh.x);
            vh.y = f2tf(v.y); vl.y = f2tf(v.y - vh.y);
            vh.z = f2tf(v.z); vl.z = f2tf(v.z - vh.z);
            vh.w = f2tf(v.w); vl.w = f2tf(v.w - vh.w);
            *(float4*)&Ah[(ar_ + 32 * p) * ASTR + ac4 * 4] = vh;
            *(float4*)&Al[(ar_ + 32 * p) * ASTR + ac4 * 4] = vl;
        }
        #pragma unroll
        for (int p = 0; p < 4; p++) {
            const float4 v = pb[p];
            float4 vh, vl;
            vh.x = f2tf(v.x); vl.x = f2tf(v.x - vh.x);
            vh.y = f2tf(v.y); vl.y = f2tf(v.y - vh.y);
            vh.z = f2tf(v.z); vl.z = f2tf(v.z - vh.z);
            vh.w = f2tf(v.w); vl.w = f2tf(v.w - vh.w);
            *(float4*)&Bh[(bkr + 8 * p) * BSTR + bc4 * 4] = vh;
            *(float4*)&Bl[(bkr + 8 * p) * BSTR + bc4 * 4] = vl;
        }
        __syncthreads();

        if (kt + 1 < ktiles) {
            const int ko = (kt + 1) * TBK;
            #pragma unroll
            for (int p = 0; p < 4; p++)
                pa[p] = *(const float4*)(A + (size_t)(row0 + ar_ + 32 * p) * K + ko + ac4 * 4);
            #pragma unroll
            for (int p = 0; p < 4; p++)
                pb[p] = *(const float4*)(B + (size_t)(ko + bkr + 8 * p) * N + col0 + bc4 * 4);
        }

        #pragma unroll
        for (int kk = 0; kk < 4; kk++) {
            const int kb = kk * 8;
            uint32_t af[4][4], bf[4][2];

            #pragma unroll
            for (int mm = 0; mm < 4; mm++) {
                const int ar = warp_m * 64 + mm * 16 + g;
                af[mm][0] = __float_as_uint(Ah[ar * ASTR + kb + tg]);
                af[mm][1] = __float_as_uint(Ah[(ar + 8) * ASTR + kb + tg]);
                af[mm][2] = __float_as_uint(Ah[ar * ASTR + kb + tg + 4]);
                af[mm][3] = __float_as_uint(Ah[(ar + 8) * ASTR + kb + tg + 4]);
            }
            #pragma unroll
            for (int nn = 0; nn < 4; nn++) {
                const int bc = warp_n * 32 + nn * 8 + g;
                bf[nn][0] = __float_as_uint(Bl[(kb + tg) * BSTR + bc]);
                bf[nn][1] = __float_as_uint(Bl[(kb + tg + 4) * BSTR + bc]);
            }
            #pragma unroll
            for (int mm = 0; mm < 4; mm++)
                #pragma unroll
                for (int nn = 0; nn < 4; nn++)
                    MMA_TF32(acc[mm][nn], af[mm][0], af[mm][1], af[mm][2], af[mm][3],
                             bf[nn][0], bf[nn][1]);
            #pragma unroll
            for (int nn = 0; nn < 4; nn++) {
                const int bc = warp_n * 32 + nn * 8 + g;
                bf[nn][0] = __float_as_uint(Bh[(kb + tg) * BSTR + bc]);
                bf[nn][1] = __float_as_uint(Bh[(kb + tg + 4) * BSTR + bc]);
            }
            #pragma unroll
            for (int mm = 0; mm < 4; mm++)
                #pragma unroll
                for (int nn = 0; nn < 4; nn++)
                    MMA_TF32(acc[mm][nn], af[mm][0], af[mm][1], af[mm][2], af[mm][3],
                             bf[nn][0], bf[nn][1]);
            #pragma unroll
            for (int mm = 0; mm < 4; mm++) {
                const int ar = warp_m * 64 + mm * 16 + g;
                af[mm][0] = __float_as_uint(Al[ar * ASTR + kb + tg]);
                af[mm][1] = __float_as_uint(Al[(ar + 8) * ASTR + kb + tg]);
                af[mm][2] = __float_as_uint(Al[ar * ASTR + kb + tg + 4]);
                af[mm][3] = __float_as_uint(Al[(ar + 8) * ASTR + kb + tg + 4]);
            }
            #pragma unroll
            for (int mm = 0; mm < 4; mm++)
                #pragma unroll
                for (int nn = 0; nn < 4; nn++)
                    MMA_TF32(acc[mm][nn], af[mm][0], af[mm][1], af[mm][2], af[mm][3],
                             bf[nn][0], bf[nn][1]);
        }
        __syncthreads();
    }

    if (mode <= 2) {
        #pragma unroll
        for (int nn = 0; nn < 4; nn++) {
            const int col = col0 + warp_n * 32 + nn * 8 + tg * 2;
            const float bv0 = bias[col], bv1 = bias[col + 1];
            #pragma unroll
            for (int mm = 0; mm < 4; mm++) {
                const int row = row0 + warp_m * 64 + mm * 16 + g;
                float2 o0, o1;
                if (mode == 0) {
                    o0.x = fmaxf(acc[mm][nn][0] + bv0, 0.f);
                    o0.y = fmaxf(acc[mm][nn][1] + bv1, 0.f);
                    o1.x = fmaxf(acc[mm][nn][2] + bv0, 0.f);
                    o1.y = fmaxf(acc[mm][nn][3] + bv1, 0.f);
                } else {
                    o0.x = acc[mm][nn][0] + bv0;
                    o0.y = acc[mm][nn][1] + bv1;
                    o1.x = acc[mm][nn][2] + bv0;
                    o1.y = acc[mm][nn][3] + bv1;
                }
                *(float2*)(C + (size_t)row * N + col)       = o0;
                *(float2*)(C + (size_t)(row + 8) * N + col) = o1;
            }
        }
    } else if (mode == 5) {
        // static edge fusion: msg = relu((acc + b) + P[src] - P[dst])
        #pragma unroll
        for (int mm = 0; mm < 4; mm++) {
            const int row = row0 + warp_m * 64 + mm * 16 + g;
            const long long s0 = load_ei(ei, row);
            const long long d0 = load_ei(ei, (long long)NE + row);
            const long long s1 = load_ei(ei, row + 8);
            const long long d1 = load_ei(ei, (long long)NE + row + 8);
            #pragma unroll
            for (int nn = 0; nn < 4; nn++) {
                const int col = col0 + warp_n * 32 + nn * 8 + tg * 2;
                const float bv0 = bias[col], bv1 = bias[col + 1];
                const float2 ps0 = *(const float2*)(P + s0 * HH + col);
                const float2 pd0 = *(const float2*)(P + d0 * HH + col);
                const float2 ps1 = *(const float2*)(P + s1 * HH + col);
                const float2 pd1 = *(const float2*)(P + d1 * HH + col);
                const float a0 = acc[mm][nn][0] + bv0;
                const float a1 = acc[mm][nn][1] + bv1;
                const float a2 = acc[mm][nn][2] + bv0;
                const float a3 = acc[mm][nn][3] + bv1;
                float2 o0, o1;
                o0.x = fmaxf(a0 + ps0.x - pd0.x, 0.f);
                o0.y = fmaxf(a1 + ps0.y - pd0.y, 0.f);
                o1.x = fmaxf(a2 + ps1.x - pd1.x, 0.f);
                o1.y = fmaxf(a3 + ps1.y - pd1.y, 0.f);
                *(float2*)(C + (size_t)row * N + col)       = o0;
                *(float2*)(C + (size_t)(row + 8) * N + col) = o1;
            }
        }
    } else {
        #pragma unroll
        for (int mm = 0; mm < 4; mm++) {
            const int row = row0 + warp_m * 64 + mm * 16 + g;
            long long d0, d1;
            if (mode == 3) {
                d0 = load_ei(ei, (long long)NE + row);
                d1 = load_ei(ei, (long long)NE + row + 8);
            } else {
                d0 = row >> 4;
                d1 = (row + 8) >> 4;
            }
            #pragma unroll
            for (int nn = 0; nn < 4; nn++) {
                const int col = col0 + warp_n * 32 + nn * 8 + tg * 2;
                const float bv0 = bias[col], bv1 = bias[col + 1];
                atomicAdd(&C[d0 * N + col],     fmaxf(acc[mm][nn][0] + bv0, 0.f));
                atomicAdd(&C[d0 * N + col + 1], fmaxf(acc[mm][nn][1] + bv1, 0.f));
                atomicAdd(&C[d1 * N + col],     fmaxf(acc[mm][nn][2] + bv0, 0.f));
                atomicAdd(&C[d1 * N + col + 1], fmaxf(acc[mm][nn][3] + bv1, 0.f));
            }
        }
    }
}

// ---------------- symmetric distance GEMM (lower triangle + mirror) ----------
__global__ __launch_bounds__(256, 2) void dist_sym_k(
    const float* __restrict__ X, const float* __restrict__ XT,
    const float* __restrict__ sq, float* __restrict__ C)
{
    const int bi = blockIdx.y, bj = blockIdx.x;
    if (bj > bi) return;

    extern __shared__ float sm[];
    float* Ah = sm;
    float* Al = sm + A_SZ;
    float* Bh = sm + 2 * A_SZ;
    float* Bl = sm + 2 * A_SZ + B_SZ;

    const int tid  = threadIdx.x;
    const int lane = tid & 31;
    const int warp = tid >> 5;
    const int warp_m = warp & 1;
    const int warp_n = warp >> 1;
    const int row0 = bi * TBM;
    const int col0 = bj * TBM;
    const int g  = lane >> 2;
    const int tg = lane & 3;

    const int ar_ = tid >> 3, ac4 = tid & 7;
    const int bkr = tid >> 5, bc4 = tid & 31;

    float acc[4][4][4];
    #pragma unroll
    for (int mm = 0; mm < 4; mm++)
        #pragma unroll
        for (int nn = 0; nn < 4; nn++)
            #pragma unroll
            for (int r = 0; r < 4; r++) acc[mm][nn][r] = 0.f;

    float4 pa[4], pb[4];
    #pragma unroll
    for (int p = 0; p < 4; p++)
        pa[p] = *(const float4*)(X + (size_t)(row0 + ar_ + 32 * p) * DD + ac4 * 4);
    #pragma unroll
    for (int p = 0; p < 4; p++)
        pb[p] = *(const float4*)(XT + (size_t)(bkr + 8 * p) * NN + col0 + bc4 * 4);

    #pragma unroll
    for (int kt = 0; kt < DD / TBK; kt++) {
        #pragma unroll
        for (int p = 0; p < 4; p++) {
            const float4 v = pa[p];
            float4 vh, vl;
            vh.x = f2tf(v.x); vl.x = f2tf(v.x - vh.x);
            vh.y = f2tf(v.y); vl.y = f2tf(v.y - vh.y);
            vh.z = f2tf(v.z); vl.z = f2tf(v.z - vh.z);
            vh.w = f2tf(v.w); vl.w = f2tf(v.w - vh.w);
            *(float4*)&Ah[(ar_ + 32 * p) * ASTR + ac4 * 4] = vh;
            *(float4*)&Al[(ar_ + 32 * p) * ASTR + ac4 * 4] = vl;
        }
        #pragma unroll
        for (int p = 0; p < 4; p++) {
            const float4 v = pb[p];
            float4 vh, vl;
            vh.x = f2tf(v.x); vl.x = f2tf(v.x - vh.x);
            vh.y = f2tf(v.y); vl.y = f2tf(v.y - vh.y);
            vh.z = f2tf(v.z); vl.z = f2tf(v.z - vh.z);
            vh.w = f2tf(v.w); vl.w = f2tf(v.w - vh.w);
            *(float4*)&Bh[(bkr + 8 * p) * BSTR + bc4 * 4] = vh;
            *(float4*)&Bl[(bkr + 8 * p) * BSTR + bc4 * 4] = vl;
        }
        __syncthreads();

        if (kt + 1 < DD / TBK) {
            const int ko = (kt + 1) * TBK;
            #pragma unroll
            for (int p = 0; p < 4; p++)
                pa[p] = *(const float4*)(X + (size_t)(row0 + ar_ + 32 * p) * DD + ko + ac4 * 4);
            #pragma unroll
            for (int p = 0; p < 4; p++)
                pb[p] = *(const float4*)(XT + (size_t)(ko + bkr + 8 * p) * NN + col0 + bc4 * 4);
        }

        #pragma unroll
        for (int kk = 0; kk < 4; kk++) {
            const int kb = kk * 8;
            uint32_t af[4][4], bf[4][2];

            #pragma unroll
            for (int mm = 0; mm < 4; mm++) {
                const int ar = warp_m * 64 + mm * 16 + g;
                af[mm][0] = __float_as_uint(Ah[ar * ASTR + kb + tg]);
                af[mm][1] = __float_as_uint(Ah[(ar + 8) * ASTR + kb + tg]);
                af[mm][2] = __float_as_uint(Ah[ar * ASTR + kb + tg + 4]);
                af[mm][3] = __float_as_uint(Ah[(ar + 8) * ASTR + kb + tg + 4]);
            }
            #pragma unroll
            for (int nn = 0; nn < 4; nn++) {
                const int bc = warp_n * 32 + nn * 8 + g;
                bf[nn][0] = __float_as_uint(Bl[(kb + tg) * BSTR + bc]);
                bf[nn][1] = __float_as_uint(Bl[(kb + tg + 4) * BSTR + bc]);
            }
            #pragma unroll
            for (int mm = 0; mm < 4; mm++)
                #pragma unroll
                for (int nn = 0; nn < 4; nn++)
                    MMA_TF32(acc[mm][nn], af[mm][0], af[mm][1], af[mm][2], af[mm][3],
                             bf[nn][0], bf[nn][1]);
            #pragma unroll
            for (int nn = 0; nn < 4; nn++) {
                const int bc = warp_n * 32 + nn * 8 + g;
                bf[nn][0] = __float_as_uint(Bh[(kb + tg) * BSTR + bc]);
                bf[nn][1] = __float_as_uint(Bh[(kb + tg + 4) * BSTR + bc]);
            }
            #pragma unroll
            for (int mm = 0; mm < 4; mm++)
                #pragma unroll
                for (int nn = 0; nn < 4; nn++)
                    MMA_TF32(acc[mm][nn], af[mm][0], af[mm][1], af[mm][2], af[mm][3],
                             bf[nn][0], bf[nn][1]);
            #pragma unroll
            for (int mm = 0; mm < 4; mm++) {
                const int ar = warp_m * 64 + mm * 16 + g;
                af[mm][0] = __float_as_uint(Al[ar * ASTR + kb + tg]);
                af[mm][1] = __float_as_uint(Al[(ar + 8) * ASTR + kb + tg]);
                af[mm][2] = __float_as_uint(Al[ar * ASTR + kb + tg + 4]);
                af[mm][3] = __float_as_uint(Al[(ar + 8) * ASTR + kb + tg + 4]);
            }
            #pragma unroll
            for (int mm = 0; mm < 4; mm++)
                #pragma unroll
                for (int nn = 0; nn < 4; nn++)
                    MMA_TF32(acc[mm][nn], af[mm][0], af[mm][1], af[mm][2], af[mm][3],
                             bf[nn][0], bf[nn][1]);
        }
        __syncthreads();
    }

    #pragma unroll
    for (int nn = 0; nn < 4; nn++) {
        const int col = col0 + warp_n * 32 + nn * 8 + tg * 2;
        const float bv0 = sq[col], bv1 = sq[col + 1];
        #pragma unroll
        for (int mm = 0; mm < 4; mm++) {
            const int row = row0 + warp_m * 64 + mm * 16 + g;
            float2 o0, o1;
            o0.x = bv0 - 2.f * acc[mm][nn][0];
            o0.y = bv1 - 2.f * acc[mm][nn][1];
            o1.x = bv0 - 2.f * acc[mm][nn][2];
            o1.y = bv1 - 2.f * acc[mm][nn][3];
            *(float2*)(C + (size_t)row * NN + col)       = o0;
            *(float2*)(C + (size_t)(row + 8) * NN + col) = o1;
        }
    }

    if (bi != bj) {
        float* Sc = sm;
        #pragma unroll
        for (int mm = 0; mm < 4; mm++) {
            const int lr = warp_m * 64 + mm * 16 + g;
            const float s0 = sq[row0 + lr], s1 = sq[row0 + lr + 8];
            #pragma unroll
            for (int nn = 0; nn < 4; nn++) {
                const int lc = warp_n * 32 + nn * 8 + tg * 2;
                Sc[lc * 132 + lr]            = s0 - 2.f * acc[mm][nn][0];
                Sc[(lc + 1) * 132 + lr]      = s0 - 2.f * acc[mm][nn][1];
                Sc[lc * 132 + lr + 8]        = s1 - 2.f * acc[mm][nn][2];
                Sc[(lc + 1) * 132 + lr + 8]  = s1 - 2.f * acc[mm][nn][3];
            }
        }
        __syncthreads();
        #pragma unroll
        for (int it = 0; it < 16; it++) {
            const int lc = warp + it * 8;
            const float4 v = *(const float4*)&Sc[lc * 132 + lane * 4];
            *(float4*)(C + (size_t)(col0 + lc) * NN + row0 + lane * 4) = v;
        }
    }
}

// ---------------- fallback SIMT GEMM (used only when N % 128 != 0) ----------
#define GBM 128
#define GBN 64
#define GBK 32

__global__ __launch_bounds__(256, 2) void gemm_k(
    const float* __restrict__ A, const float* __restrict__ B,
    const float* __restrict__ bias, float* __restrict__ C,
    int M, int K, int N, int mode)
{
    __shared__ float As[GBK][GBM + 4];
    __shared__ float Bs[GBK][GBN];
    const int tid  = threadIdx.x;
    const int row0 = blockIdx.y * GBM;
    const int col0 = blockIdx.x * GBN;
    const int tr = tid >> 4;
    const int tc = tid & 15;

    float acc[8][4];
    #pragma unroll
    for (int i = 0; i < 8; i++)
        #pragma unroll
        for (int j = 0; j < 4; j++) acc[i][j] = 0.f;

    const int ktiles = K / GBK;
    for (int kt = 0; kt < ktiles; kt++) {
        #pragma unroll
        for (int p = 0; p < 4; p++) {
            int lin = tid + 256 * p;
            int r = lin >> 3, q = lin & 7;
            const float4 v = *(const float4*)(A + (size_t)(row0 + r) * K + kt * GBK + q * 4);
            As[q * 4 + 0][r] = v.x; As[q * 4 + 1][r] = v.y;
            As[q * 4 + 2][r] = v.z; As[q * 4 + 3][r] = v.w;
        }
        #pragma unroll
        for (int p = 0; p < 2; p++) {
            int lin = tid + 256 * p;
            int kr = lin >> 4, j4 = lin & 15;
            *(float4*)&Bs[kr][j4 * 4] =
                *(const float4*)(B + (size_t)(kt * GBK + kr) * N + col0 + j4 * 4);
        }
        __syncthreads();
        #pragma unroll
        for (int k = 0; k < GBK; k++) {
            float a[8], b[4];
            *(float4*)&a[0] = *(const float4*)&As[k][tr * 8];
            *(float4*)&a[4] = *(const float4*)&As[k][tr * 8 + 4];
            *(float4*)&b[0] = *(const float4*)&Bs[k][tc * 4];
            #pragma unroll
            for (int i = 0; i < 8; i++)
                #pragma unroll
                for (int j = 0; j < 4; j++)
                    acc[i][j] = fmaf(a[i], b[j], acc[i][j]);
        }
        __syncthreads();
    }

    float bv[4];
    #pragma unroll
    for (int j = 0; j < 4; j++) bv[j] = bias[col0 + tc * 4 + j];

    #pragma unroll
    for (int i = 0; i < 8; i++) {
        const int row = row0 + tr * 8 + i;
        float4 o;
        o.x = fmaxf(acc[i][0] + bv[0], 0.f);
        o.y = fmaxf(acc[i][1] + bv[1], 0.f);
        o.z = fmaxf(acc[i][2] + bv[2], 0.f);
        o.w = fmaxf(acc[i][3] + bv[3], 0.f);
        *(float4*)(C + (size_t)row * N + col0 + tc * 4) = o;
    }
}

// ---------------- dynamic fusion (factored first MLP layer) ------------------
// hid[e=i*16+t] = relu(Pd[i] + P2[knn[e]] + b), Pd = xd @ (W_top - W_bot)
__global__ __launch_bounds__(256) void dyn_fuse_k(
    const float* __restrict__ Pd, const float* __restrict__ P2,
    const int* __restrict__ knn, const float* __restrict__ bias,
    float* __restrict__ hid)
{
    const int e  = blockIdx.x * 4 + (threadIdx.x >> 6);
    const int c4 = threadIdx.x & 63;
    const int i = e >> 4;
    const int j = knn[e];
    const float4 pd = *(const float4*)(Pd + (size_t)i * HH + c4 * 4);
    const float4 pj = *(const float4*)(P2 + (size_t)j * HH + c4 * 4);
    const float4 b  = *(const float4*)(bias + c4 * 4);
    float4 o;
    o.x = fmaxf(pd.x + pj.x + b.x, 0.f);
    o.y = fmaxf(pd.y + pj.y + b.y, 0.f);
    o.z = fmaxf(pd.z + pj.z + b.z, 0.f);
    o.w = fmaxf(pd.w + pj.w + b.w, 0.f);
    *(float4*)(hid + (size_t)e * HH + c4 * 4) = o;
}

// Wd = W_top - W_bot  (DD*HH elements)
__global__ void wdiff_k(const float* __restrict__ W1, float* __restrict__ Wd)
{
    const int idx = blockIdx.x * 256 + threadIdx.x;
    Wd[idx] = W1[idx] - W1[DD * HH + idx];
}

// ---------------- small helper kernels --------------------------------------
__global__ void rownorm_k(const float* __restrict__ x, float* __restrict__ sq)
{
    const int row  = blockIdx.x * 8 + (threadIdx.x >> 5);
    const int lane = threadIdx.x & 31;
    const float* p = x + (size_t)row * DD;
    float s = 0.f;
    #pragma unroll
    for (int q = 0; q < 4; q++) { float v = p[lane + 32 * q]; s = fmaf(v, v, s); }
    #pragma unroll
    for (int o = 16; o > 0; o >>= 1) s += __shfl_xor_sync(0xffffffffu, s, o);
    if (lane == 0) sq[row] = s;
}

__global__ void transpose_k(const float* __restrict__ in, float* __restrict__ out)
{
    __shared__ float t[32][33];
    const int j0 = blockIdx.x * 32, k0 = blockIdx.y * 32;
    for (int r = threadIdx.y; r < 32; r += 8)
        t[r][threadIdx.x] = in[(size_t)(j0 + r) * DD + k0 + threadIdx.x];
    __syncthreads();
    for (int r = threadIdx.y; r < 32; r += 8)
        out[(size_t)(k0 + r) * NN + j0 + threadIdx.x] = t[threadIdx.x][r];
}

// ---------------- top-16: u64 keys, SLOT-MAJOR smem queues -------------------
__global__ __launch_bounds__(256) void topk_k(const float* __restrict__ dist,
                                              int* __restrict__ knn)
{
    __shared__ unsigned long long sk[KK * 256];   // 32 KB, slot-major
    const unsigned long long SENT = 0xFF800000FFFFFFFFull;  // (+inf, idxmax)
    const int tid = threadIdx.x;
    const int rr  = tid >> 4;          // row within block
    const int tt  = tid & 15;          // thread within row
    const int row_g = blockIdx.x * 16 + rr;
    const float* row = dist + (size_t)row_g * NN;

    #pragma unroll
    for (int q = 0; q < KK; q++) sk[q * 256 + tid] = SENT;
    unsigned long long worst_key = SENT;
    float worstf = __int_as_float(0x7f800000);   // +inf

    for (int c = 0; c < NN / 64; c++) {
        const float4 v = *(const float4*)(row + c * 64 + tt * 4);
        const float mn = fminf(fminf(v.x, v.y), fminf(v.z, v.w));
        if (mn <= worstf) {
            const int j0 = c * 64 + tt * 4;
            const float vv[4] = { v.x, v.y, v.z, v.w };
            #pragma unroll
            for (int u = 0; u < 4; u++) {
                uint32_t ou = __float_as_uint(vv[u]);
                ou = (ou & 0x80000000u) ? ~ou : (ou | 0x80000000u);
                const unsigned long long key =
                    ((unsigned long long)ou << 32) | (uint32_t)(j0 + u);
                if (key < worst_key) {
                    int p = KK - 1;
                    while (p > 0 && sk[(p - 1) * 256 + tid] > key) {
                        sk[p * 256 + tid] = sk[(p - 1) * 256 + tid];
                        p--;
                    }
                    sk[p * 256 + tid] = key;
                    worst_key = sk[(KK - 1) * 256 + tid];
                    uint32_t wo = (uint32_t)(worst_key >> 32);
                    wo = (wo & 0x80000000u) ? (wo ^ 0x80000000u) : ~wo;
                    worstf = __uint_as_float(wo);
                }
            }
        }
    }

    for (int s = 8; s > 0; s >>= 1) {
        __syncthreads();
        if (tt < s) {
            const int ca = rr * 16 + tt;
            const int cb = rr * 16 + tt + s;
            unsigned long long out[KK];
            int pa = 0, pb = 0;
            #pragma unroll
            for (int q = 0; q < KK; q++) {
                const unsigned long long ka = sk[pa * 256 + ca];
                const unsigned long long kb = sk[pb * 256 + cb];
                if (ka <= kb) { out[q] = ka; pa++; }
                else          { out[q] = kb; pb++; }
            }
            #pragma unroll
            for (int q = 0; q < KK; q++) sk[q * 256 + ca] = out[q];
        }
    }
    __syncthreads();
    knn[row_g * KK + tt] = (int)(sk[tt * 256 + rr * 16] & 0xFFFFFFFFu);
}

__global__ void concat_k(const float* __restrict__ a, const float* __restrict__ b,
                         float* __restrict__ out)
{
    const int i = blockIdx.x, c = threadIdx.x;
    out[(size_t)i * 256 + c] = (c < DD) ? a[i * DD + c] : b[i * DD + c - DD];
}

// ---------------- host orchestration ---------------------------------------
static inline void gemm(const float* A, const float* B, const float* bias, float* C,
                        int M, int K, int N, int mode, const void* ei = nullptr,
                        const float* P = nullptr)
{
    if ((N % TBN) == 0 && (M % TBM) == 0) {
        dim3 g(N / TBN, M / TBM);
        mma3_gemm_k<<<g, 256, MMA3_SMEM_BYTES>>>(A, B, bias, C, M, K, N, mode, ei, P);
    } else {
        dim3 g(N / GBN, M / GBM);
        gemm_k<<<g, 256>>>(A, B, bias, C, M, K, N, mode);
    }
}

extern "C" void kernel_launch(void* const* d_in, const int* in_sizes, int n_in,
                              void* d_out, int out_size)
{
    const float* x    = (const float*)d_in[0];
    const float* ea_i = (const float*)d_in[1];
    const float* sW1  = (const float*)d_in[2];
    const float* sb1  = (const float*)d_in[3];
    const float* sW2  = (const float*)d_in[4];
    const float* sb2  = (const float*)d_in[5];
    const float* uW1  = (const float*)d_in[6];
    const float* ub1  = (const float*)d_in[7];
    const float* uW2  = (const float*)d_in[8];
    const float* ub2  = (const float*)d_in[9];
    const float* rW   = (const float*)d_in[10];
    const float* rb   = (const float*)d_in[11];
    const float* dW1  = (const float*)d_in[12];
    const float* db1  = (const float*)d_in[13];
    const float* dW2  = (const float*)d_in[14];
    const float* db2  = (const float*)d_in[15];
    const float* dUW1 = (const float*)d_in[16];
    const float* dUb1 = (const float*)d_in[17];
    const float* dUW2 = (const float*)d_in[18];
    const float* dUb2 = (const float*)d_in[19];
    const float* fW1  = (const float*)d_in[20];
    const float* fb1  = (const float*)d_in[21];
    const float* fW2  = (const float*)d_in[22];
    const float* fb2  = (const float*)d_in[23];
    const void*  ei   = d_in[24];

    cudaFuncSetAttribute(mma3_gemm_k, cudaFuncAttributeMaxDynamicSharedMemorySize,
                         MMA3_SMEM_BYTES);
    cudaFuncSetAttribute(dist_sym_k, cudaFuncAttributeMaxDynamicSharedMemorySize,
                         MMA3_SMEM_BYTES);

    float *msg, *ea0, *ea1, *xs0, *xs1, *xd0, *xd1;
    float *agg, *tmpN, *P2, *cat, *sq, *xT, *dist, *zero, *Wd;
    int   *knn;
    cudaGetSymbolAddress((void**)&msg,  g_msg);
    cudaGetSymbolAddress((void**)&ea0,  g_ea0);
    cudaGetSymbolAddress((void**)&ea1,  g_ea1);
    cudaGetSymbolAddress((void**)&xs0,  g_xs0);
    cudaGetSymbolAddress((void**)&xs1,  g_xs1);
    cudaGetSymbolAddress((void**)&xd0,  g_xd0);
    cudaGetSymbolAddress((void**)&xd1,  g_xd1);
    cudaGetSymbolAddress((void**)&agg,  g_agg);
    cudaGetSymbolAddress((void**)&tmpN, g_tmpN);
    cudaGetSymbolAddress((void**)&P2,   g_P2);
    cudaGetSymbolAddress((void**)&cat,  g_cat);
    cudaGetSymbolAddress((void**)&sq,   g_sq);
    cudaGetSymbolAddress((void**)&xT,   g_xT);
    cudaGetSymbolAddress((void**)&dist, g_dist);
    cudaGetSymbolAddress((void**)&zero, g_zero);
    cudaGetSymbolAddress((void**)&Wd,   g_Wd);
    cudaGetSymbolAddress((void**)&knn,  g_knn);

    detect_ei_k<<<1, 1>>>(ei);

    // ---------------- static branch: 3 conv layers + 2 edge refiners --------
    // msg = relu(ea@W_e + b1 + (xs@W_x)[src] - (xs@W_x)[dst])  [mode-5 epilogue]
    const float* xs_in = x;
    const float* ea_in = ea_i;
    float* xs_bufs[2] = { xs0, xs1 };
    float* ea_bufs[2] = { ea0, ea1 };
    for (int i = 0; i < 3; i++) {
        const float* W1 = sW1 + (size_t)i * 192 * HH;
        gemm(xs_in, W1 + (size_t)DE * HH, zero, tmpN, NN, DD, HH, 2);   // P = xs@W_x
        gemm(ea_in, W1, sb1 + i * HH, msg, NE, DE, HH, 5, ei, tmpN);    // fused msg
        cudaMemsetAsync(agg, 0, (size_t)NN * DD * sizeof(float));
        gemm(msg, sW2 + (size_t)i * HH * DD, sb2 + i * DD, agg, NE, HH, DD, 3, ei);
        gemm(agg,  uW1 + (size_t)i * DD * HH, ub1 + i * HH, tmpN, NN, DD, HH, 0);
        float* xs_out = xs_bufs[i & 1];
        gemm(tmpN, uW2 + (size_t)i * HH * DD, ub2 + i * DD, xs_out, NN, HH, DD, 0);
        if (i < 2) {
            float* ea_out = ea_bufs[i & 1];
            gemm(ea_in, rW + (size_t)i * DE * DE, rb + i * DE, ea_out, NE, DE, DE, 0);
            ea_in = ea_out;
        }
        xs_in = xs_out;
    }

    // ---------------- dynamic branch: 2 kNN conv layers ---------------------
    // Pd = xd @ (W_top - W_bot);  P2 = xd @ W_bot;  msg = relu(Pd[i]+P2[j]+b)
    const float* xd_in = x;
    float* xd_bufs[2] = { xd0, xd1 };
    for (int i = 0; i < 2; i++) {
        rownorm_k<<<NN / 8, 256>>>(xd_in, sq);
        transpose_k<<<dim3(NN / 32, DD / 32), dim3(32, 8)>>>(xd_in, xT);
        dist_sym_k<<<dim3(NN / TBM, NN / TBM), 256, MMA3_SMEM_BYTES>>>(xd_in, xT, sq, dist);
        topk_k<<<NN / 16, 256>>>(dist, knn);
        const float* W1 = dW1 + (size_t)i * 2 * DD * HH;
        wdiff_k<<<DD * HH / 256, 256>>>(W1, Wd);
        gemm(xd_in, Wd, zero, tmpN, NN, DD, HH, 2);                     // Pd
        gemm(xd_in, W1 + (size_t)DD * HH, zero, P2, NN, DD, HH, 2);     // P2
        dyn_fuse_k<<<NE / 4, 256>>>(tmpN, P2, knn, db1 + i * HH, msg);
        cudaMemsetAsync(agg, 0, (size_t)NN * DD * sizeof(float));
        gemm(msg, dW2 + (size_t)i * HH * DD, db2 + i * DD, agg, NE, HH, DD, 4);
        gemm(agg,  dUW1 + (size_t)i * DD * HH, dUb1 + i * HH, tmpN, NN, DD, HH, 0);
        float* xd_out = xd_bufs[i];
        gemm(tmpN, dUW2 + (size_t)i * HH * DD, dUb2 + i * DD, xd_out, NN, HH, DD, 0);
        xd_in = xd_out;
    }

    // ---------------- fuse ---------------------------------------------------
    concat_k<<<NN, 256>>>(xs_in, xd_in, cat);
    gemm(cat,  fW1, fb1, tmpN, NN, 2 * DD, HH, 0);
    gemm(tmpN, fW2, fb2, (float*)d_out, NN, HH, DD, 0);
}

// round 14
// speedup vs baseline: 2.1610x; 1.0589x over previous
#include <cuda_runtime.h>
#include <cstdint>
#include <cstddef>

// ---------------- problem constants (fixed by the dataset) ----------------
#define NN   16384      // nodes
#define NE   262144     // static edges (== NN * 16, also dynamic edge count)
#define DD   128        // node dim
#define DE   64         // edge dim
#define HH   256        // hidden
#define KK   16         // kNN

// ---------------- device scratch (allocation-free rule: __device__ globals) ----
// static branch buffers
__device__ float g_msg [(size_t)NE * 256];
__device__ float g_ea0 [(size_t)NE * DE];
__device__ float g_ea1 [(size_t)NE * DE];
__device__ float g_xs0 [NN * DD];
__device__ float g_xs1 [NN * DD];
__device__ float g_agg [NN * DD];
__device__ float g_tmpN[NN * HH];
// dynamic branch buffers (disjoint so the branches can run concurrently)
__device__ float g_msg2[(size_t)NE * 256];
__device__ float g_xd0 [NN * DD];
__device__ float g_xd1 [NN * DD];
__device__ float g_agg2[NN * DD];
__device__ float g_Pd  [NN * HH];
__device__ float g_P2  [NN * HH];
__device__ float g_sq  [NN];
__device__ float g_xT  [(size_t)DD * NN];
__device__ float g_dist[(size_t)NN * NN];
__device__ int   g_knn [NN * KK];
__device__ float g_Wd  [DD * HH];     // W_top - W_bot
// shared
__device__ float g_cat [NN * 2 * DD];
__device__ float g_zero[HH];          // zero-initialized bias
__device__ int   g_ei64flag;

// ---------------- edge_index dtype handling (int64 vs silently-int32) -----
__global__ void detect_ei_k(const void* p) {
    const unsigned long long* q = (const unsigned long long*)p;
    int ok = 1;
    #pragma unroll
    for (int i = 0; i < 8; i++)
        if (q[i] >= (unsigned long long)NN) ok = 0;
    g_ei64flag = ok;
}

__device__ __forceinline__ long long load_ei(const void* p, long long idx) {
    if (g_ei64flag) return ((const long long*)p)[idx];
    return (long long)((const int*)p)[idx];
}

// ---------------- tf32 helpers ----------------------------------------------
__device__ __forceinline__ float f2tf(float x) {
    uint32_t u;
    asm("cvt.rna.tf32.f32 %0, %1;" : "=r"(u) : "f"(x));
    return __uint_as_float(u);
}

#define MMA_TF32(acc, a0, a1, a2, a3, b0, b1)                                  \
    asm volatile(                                                              \
        "mma.sync.aligned.m16n8k8.row.col.f32.tf32.tf32.f32 "                  \
        "{%0,%1,%2,%3}, {%4,%5,%6,%7}, {%8,%9}, {%0,%1,%2,%3};"                \
        : "+f"(acc[0]), "+f"(acc[1]), "+f"(acc[2]), "+f"(acc[3])               \
        : "r"(a0), "r"(a1), "r"(a2), "r"(a3), "r"(b0), "r"(b1))

#define TBM 128
#define TBN 128
#define TBK 32
#define ASTR 36
#define BSTR 136
#define A_SZ (TBM * ASTR)
#define B_SZ (TBK * BSTR)
#define MMA3_SMEM_BYTES ((2 * A_SZ + 2 * B_SZ) * 4)   // 71680 B

// ---------------- 3xTF32 tensor-core GEMM (fp32-accurate) --------------------
// mode 0: relu(acc+bias) store; mode 2: acc+bias store
// mode 3: relu(acc+bias) atomicAdd into C[ei[NE+row]*N + col]
// mode 4: relu(acc+bias) atomicAdd into C[(row>>4)*N + col]
// mode 5: relu(acc+bias + P[ei[row]] - P[ei[NE+row]]) store (N == HH)
__global__ __launch_bounds__(256, 2) void mma3_gemm_k(
    const float* __restrict__ A, const float* __restrict__ B,
    const float* __restrict__ bias, float* __restrict__ C,
    int M, int K, int N, int mode, const void* __restrict__ ei,
    const float* __restrict__ P)
{
    extern __shared__ float sm[];
    float* Ah = sm;
    float* Al = sm + A_SZ;
    float* Bh = sm + 2 * A_SZ;
    float* Bl = sm + 2 * A_SZ + B_SZ;

    const int tid  = threadIdx.x;
    const int lane = tid & 31;
    const int warp = tid >> 5;
    const int warp_m = warp & 1;
    const int warp_n = warp >> 1;
    const int row0 = blockIdx.y * TBM;
    const int col0 = blockIdx.x * TBN;
    const int g  = lane >> 2;
    const int tg = lane & 3;

    const int ar_ = tid >> 3, ac4 = tid & 7;
    const int bkr = tid >> 5, bc4 = tid & 31;

    float acc[4][4][4];
    #pragma unroll
    for (int mm = 0; mm < 4; mm++)
        #pragma unroll
        for (int nn = 0; nn < 4; nn++)
            #pragma unroll
            for (int r = 0; r < 4; r++) acc[mm][nn][r] = 0.f;

    const int ktiles = K / TBK;

    float4 pa[4], pb[4];
    #pragma unroll
    for (int p = 0; p < 4; p++)
        pa[p] = *(const float4*)(A + (size_t)(row0 + ar_ + 32 * p) * K + ac4 * 4);
    #pragma unroll
    for (int p = 0; p < 4; p++)
        pb[p] = *(const float4*)(B + (size_t)(bkr + 8 * p) * N + col0 + bc4 * 4);

    for (int kt = 0; kt < ktiles; kt++) {
        #pragma unroll
        for (int p = 0; p < 4; p++) {
            const float4 v = pa[p];
            float4 vh, vl;
            vh.x = f2tf(v.x); vl.x = f2tf(v.x - vh.x);
            vh.y = f2tf(v.y); vl.y = f2tf(v.y - vh.y);
            vh.z = f2tf(v.z); vl.z = f2tf(v.z - vh.z);
            vh.w = f2tf(v.w); vl.w = f2tf(v.w - vh.w);
            *(float4*)&Ah[(ar_ + 32 * p) * ASTR + ac4 * 4] = vh;
            *(float4*)&Al[(ar_ + 32 * p) * ASTR + ac4 * 4] = vl;
        }
        #pragma unroll
        for (int p = 0; p < 4; p++) {
            const float4 v = pb[p];
            float4 vh, vl;
            vh.x = f2tf(v.x); vl.x = f2tf(v.x - vh.x);
            vh.y = f2tf(v.y); vl.y = f2tf(v.y - vh.y);
            vh.z = f2tf(v.z); vl.z = f2tf(v.z - vh.z);
            vh.w = f2tf(v.w); vl.w = f2tf(v.w - vh.w);
            *(float4*)&Bh[(bkr + 8 * p) * BSTR + bc4 * 4] = vh;
            *(float4*)&Bl[(bkr + 8 * p) * BSTR + bc4 * 4] = vl;
        }
        __syncthreads();

        if (kt + 1 < ktiles) {
            const int ko = (kt + 1) * TBK;
            #pragma unroll
            for (int p = 0; p < 4; p++)
                pa[p] = *(const float4*)(A + (size_t)(row0 + ar_ + 32 * p) * K + ko + ac4 * 4);
            #pragma unroll
            for (int p = 0; p < 4; p++)
                pb[p] = *(const float4*)(B + (size_t)(ko + bkr + 8 * p) * N + col0 + bc4 * 4);
        }

        #pragma unroll
        for (int kk = 0; kk < 4; kk++) {
            const int kb = kk * 8;
            uint32_t af[4][4], bf[4][2];

            #pragma unroll
            for (int mm = 0; mm < 4; mm++) {
                const int ar = warp_m * 64 + mm * 16 + g;
                af[mm][0] = __float_as_uint(Ah[ar * ASTR + kb + tg]);
                af[mm][1] = __float_as_uint(Ah[(ar + 8) * ASTR + kb + tg]);
                af[mm][2] = __float_as_uint(Ah[ar * ASTR + kb + tg + 4]);
                af[mm][3] = __float_as_uint(Ah[(ar + 8) * ASTR + kb + tg + 4]);
            }
            #pragma unroll
            for (int nn = 0; nn < 4; nn++) {
                const int bc = warp_n * 32 + nn * 8 + g;
                bf[nn][0] = __float_as_uint(Bl[(kb + tg) * BSTR + bc]);
                bf[nn][1] = __float_as_uint(Bl[(kb + tg + 4) * BSTR + bc]);
            }
            #pragma unroll
            for (int mm = 0; mm < 4; mm++)
                #pragma unroll
                for (int nn = 0; nn < 4; nn++)
                    MMA_TF32(acc[mm][nn], af[mm][0], af[mm][1], af[mm][2], af[mm][3],
                             bf[nn][0], bf[nn][1]);
            #pragma unroll
            for (int nn = 0; nn < 4; nn++) {
                const int bc = warp_n * 32 + nn * 8 + g;
                bf[nn][0] = __float_as_uint(Bh[(kb + tg) * BSTR + bc]);
                bf[nn][1] = __float_as_uint(Bh[(kb + tg + 4) * BSTR + bc]);
            }
            #pragma unroll
            for (int mm = 0; mm < 4; mm++)
                #pragma unroll
                for (int nn = 0; nn < 4; nn++)
                    MMA_TF32(acc[mm][nn], af[mm][0], af[mm][1], af[mm][2], af[mm][3],
                             bf[nn][0], bf[nn][1]);
            #pragma unroll
            for (int mm = 0; mm < 4; mm++) {
                const int ar = warp_m * 64 + mm * 16 + g;
                af[mm][0] = __float_as_uint(Al[ar * ASTR + kb + tg]);
                af[mm][1] = __float_as_uint(Al[(ar + 8) * ASTR + kb + tg]);
                af[mm][2] = __float_as_uint(Al[ar * ASTR + kb + tg + 4]);
                af[mm][3] = __float_as_uint(Al[(ar + 8) * ASTR + kb + tg + 4]);
            }
            #pragma unroll
            for (int mm = 0; mm < 4; mm++)
                #pragma unroll
                for (int nn = 0; nn < 4; nn++)
                    MMA_TF32(acc[mm][nn], af[mm][0], af[mm][1], af[mm][2], af[mm][3],
                             bf[nn][0], bf[nn][1]);
        }
        __syncthreads();
    }

    if (mode <= 2) {
        #pragma unroll
        for (int nn = 0; nn < 4; nn++) {
            const int col = col0 + warp_n * 32 + nn * 8 + tg * 2;
            const float bv0 = bias[col], bv1 = bias[col + 1];
            #pragma unroll
            for (int mm = 0; mm < 4; mm++) {
                const int row = row0 + warp_m * 64 + mm * 16 + g;
                float2 o0, o1;
                if (mode == 0) {
                    o0.x = fmaxf(acc[mm][nn][0] + bv0, 0.f);
                    o0.y = fmaxf(acc[mm][nn][1] + bv1, 0.f);
                    o1.x = fmaxf(acc[mm][nn][2] + bv0, 0.f);
                    o1.y = fmaxf(acc[mm][nn][3] + bv1, 0.f);
                } else {
                    o0.x = acc[mm][nn][0] + bv0;
                    o0.y = acc[mm][nn][1] + bv1;
                    o1.x = acc[mm][nn][2] + bv0;
                    o1.y = acc[mm][nn][3] + bv1;
                }
                *(float2*)(C + (size_t)row * N + col)       = o0;
                *(float2*)(C + (size_t)(row + 8) * N + col) = o1;
            }
        }
    } else if (mode == 5) {
        #pragma unroll
        for (int mm = 0; mm < 4; mm++) {
            const int row = row0 + warp_m * 64 + mm * 16 + g;
            const long long s0 = load_ei(ei, row);
            const long long d0 = load_ei(ei, (long long)NE + row);
            const long long s1 = load_ei(ei, row + 8);
            const long long d1 = load_ei(ei, (long long)NE + row + 8);
            #pragma unroll
            for (int nn = 0; nn < 4; nn++) {
                const int col = col0 + warp_n * 32 + nn * 8 + tg * 2;
                const float bv0 = bias[col], bv1 = bias[col + 1];
                const float2 ps0 = *(const float2*)(P + s0 * HH + col);
                const float2 pd0 = *(const float2*)(P + d0 * HH + col);
                const float2 ps1 = *(const float2*)(P + s1 * HH + col);
                const float2 pd1 = *(const float2*)(P + d1 * HH + col);
                const float a0 = acc[mm][nn][0] + bv0;
                const float a1 = acc[mm][nn][1] + bv1;
                const float a2 = acc[mm][nn][2] + bv0;
                const float a3 = acc[mm][nn][3] + bv1;
                float2 o0, o1;
                o0.x = fmaxf(a0 + ps0.x - pd0.x, 0.f);
                o0.y = fmaxf(a1 + ps0.y - pd0.y, 0.f);
                o1.x = fmaxf(a2 + ps1.x - pd1.x, 0.f);
                o1.y = fmaxf(a3 + ps1.y - pd1.y, 0.f);
                *(float2*)(C + (size_t)row * N + col)       = o0;
                *(float2*)(C + (size_t)(row + 8) * N + col) = o1;
            }
        }
    } else {
        #pragma unroll
        for (int mm = 0; mm < 4; mm++) {
            const int row = row0 + warp_m * 64 + mm * 16 + g;
            long long d0, d1;
            if (mode == 3) {
                d0 = load_ei(ei, (long long)NE + row);
                d1 = load_ei(ei, (long long)NE + row + 8);
            } else {
                d0 = row >> 4;
                d1 = (row + 8) >> 4;
            }
            #pragma unroll
            for (int nn = 0; nn < 4; nn++) {
                const int col = col0 + warp_n * 32 + nn * 8 + tg * 2;
                const float bv0 = bias[col], bv1 = bias[col + 1];
                atomicAdd(&C[d0 * N + col],     fmaxf(acc[mm][nn][0] + bv0, 0.f));
                atomicAdd(&C[d0 * N + col + 1], fmaxf(acc[mm][nn][1] + bv1, 0.f));
                atomicAdd(&C[d1 * N + col],     fmaxf(acc[mm][nn][2] + bv0, 0.f));
                atomicAdd(&C[d1 * N + col + 1], fmaxf(acc[mm][nn][3] + bv1, 0.f));
            }
        }
    }
}

// ---------------- symmetric distance GEMM (lower triangle + mirror) ----------
__global__ __launch_bounds__(256, 2) void dist_sym_k(
    const float* __restrict__ X, const float* __restrict__ XT,
    const float* __restrict__ sq, float* __restrict__ C)
{
    const int bi = blockIdx.y, bj = blockIdx.x;
    if (bj > bi) return;

    extern __shared__ float sm[];
    float* Ah = sm;
    float* Al = sm + A_SZ;
    float* Bh = sm + 2 * A_SZ;
    float* Bl = sm + 2 * A_SZ + B_SZ;

    const int tid  = threadIdx.x;
    const int lane = tid & 31;
    const int warp = tid >> 5;
    const int warp_m = warp & 1;
    const int warp_n = warp >> 1;
    const int row0 = bi * TBM;
    const int col0 = bj * TBM;
    const int g  = lane >> 2;
    const int tg = lane & 3;

    const int ar_ = tid >> 3, ac4 = tid & 7;
    const int bkr = tid >> 5, bc4 = tid & 31;

    float acc[4][4][4];
    #pragma unroll
    for (int mm = 0; mm < 4; mm++)
        #pragma unroll
        for (int nn = 0; nn < 4; nn++)
            #pragma unroll
            for (int r = 0; r < 4; r++) acc[mm][nn][r] = 0.f;

    float4 pa[4], pb[4];
    #pragma unroll
    for (int p = 0; p < 4; p++)
        pa[p] = *(const float4*)(X + (size_t)(row0 + ar_ + 32 * p) * DD + ac4 * 4);
    #pragma unroll
    for (int p = 0; p < 4; p++)
        pb[p] = *(const float4*)(XT + (size_t)(bkr + 8 * p) * NN + col0 + bc4 * 4);

    #pragma unroll
    for (int kt = 0; kt < DD / TBK; kt++) {
        #pragma unroll
        for (int p = 0; p < 4; p++) {
            const float4 v = pa[p];
            float4 vh, vl;
            vh.x = f2tf(v.x); vl.x = f2tf(v.x - vh.x);
            vh.y = f2tf(v.y); vl.y = f2tf(v.y - vh.y);
            vh.z = f2tf(v.z); vl.z = f2tf(v.z - vh.z);
            vh.w = f2tf(v.w); vl.w = f2tf(v.w - vh.w);
            *(float4*)&Ah[(ar_ + 32 * p) * ASTR + ac4 * 4] = vh;
            *(float4*)&Al[(ar_ + 32 * p) * ASTR + ac4 * 4] = vl;
        }
        #pragma unroll
        for (int p = 0; p < 4; p++) {
            const float4 v = pb[p];
            float4 vh, vl;
            vh.x = f2tf(v.x); vl.x = f2tf(v.x - vh.x);
            vh.y = f2tf(v.y); vl.y = f2tf(v.y - vh.y);
            vh.z = f2tf(v.z); vl.z = f2tf(v.z - vh.z);
            vh.w = f2tf(v.w); vl.w = f2tf(v.w - vh.w);
            *(float4*)&Bh[(bkr + 8 * p) * BSTR + bc4 * 4] = vh;
            *(float4*)&Bl[(bkr + 8 * p) * BSTR + bc4 * 4] = vl;
        }
        __syncthreads();

        if (kt + 1 < DD / TBK) {
            const int ko = (kt + 1) * TBK;
            #pragma unroll
            for (int p = 0; p < 4; p++)
                pa[p] = *(const float4*)(X + (size_t)(row0 + ar_ + 32 * p) * DD + ko + ac4 * 4);
            #pragma unroll
            for (int p = 0; p < 4; p++)
                pb[p] = *(const float4*)(XT + (size_t)(ko + bkr + 8 * p) * NN + col0 + bc4 * 4);
        }

        #pragma unroll
        for (int kk = 0; kk < 4; kk++) {
            const int kb = kk * 8;
            uint32_t af[4][4], bf[4][2];

            #pragma unroll
            for (int mm = 0; mm < 4; mm++) {
                const int ar = warp_m * 64 + mm * 16 + g;
                af[mm][0] = __float_as_uint(Ah[ar * ASTR + kb + tg]);
                af[mm][1] = __float_as_uint(Ah[(ar + 8) * ASTR + kb + tg]);
                af[mm][2] = __float_as_uint(Ah[ar * ASTR + kb + tg + 4]);
                af[mm][3] = __float_as_uint(Ah[(ar + 8) * ASTR + kb + tg + 4]);
            }
            #pragma unroll
            for (int nn = 0; nn < 4; nn++) {
                const int bc = warp_n * 32 + nn * 8 + g;
                bf[nn][0] = __float_as_uint(Bl[(kb + tg) * BSTR + bc]);
                bf[nn][1] = __float_as_uint(Bl[(kb + tg + 4) * BSTR + bc]);
            }
            #pragma unroll
            for (int mm = 0; mm < 4; mm++)
                #pragma unroll
                for (int nn = 0; nn < 4; nn++)
                    MMA_TF32(acc[mm][nn], af[mm][0], af[mm][1], af[mm][2], af[mm][3],
                             bf[nn][0], bf[nn][1]);
            #pragma unroll
            for (int nn = 0; nn < 4; nn++) {
                const int bc = warp_n * 32 + nn * 8 + g;
                bf[nn][0] = __float_as_uint(Bh[(kb + tg) * BSTR + bc]);
                bf[nn][1] = __float_as_uint(Bh[(kb + tg + 4) * BSTR + bc]);
            }
            #pragma unroll
            for (int mm = 0; mm < 4; mm++)
                #pragma unroll
                for (int nn = 0; nn < 4; nn++)
                    MMA_TF32(acc[mm][nn], af[mm][0], af[mm][1], af[mm][2], af[mm][3],
                             bf[nn][0], bf[nn][1]);
            #pragma unroll
            for (int mm = 0; mm < 4; mm++) {
                const int ar = warp_m * 64 + mm * 16 + g;
                af[mm][0] = __float_as_uint(Al[ar * ASTR + kb + tg]);
                af[mm][1] = __float_as_uint(Al[(ar + 8) * ASTR + kb + tg]);
                af[mm][2] = __float_as_uint(Al[ar * ASTR + kb + tg + 4]);
                af[mm][3] = __float_as_uint(Al[(ar + 8) * ASTR + kb + tg + 4]);
            }
            #pragma unroll
            for (int mm = 0; mm < 4; mm++)
                #pragma unroll
                for (int nn = 0; nn < 4; nn++)
                    MMA_TF32(acc[mm][nn], af[mm][0], af[mm][1], af[mm][2], af[mm][3],
                             bf[nn][0], bf[nn][1]);
        }
        __syncthreads();
    }

    #pragma unroll
    for (int nn = 0; nn < 4; nn++) {
        const int col = col0 + warp_n * 32 + nn * 8 + tg * 2;
        const float bv0 = sq[col], bv1 = sq[col + 1];
        #pragma unroll
        for (int mm = 0; mm < 4; mm++) {
            const int row = row0 + warp_m * 64 + mm * 16 + g;
            float2 o0, o1;
            o0.x = bv0 - 2.f * acc[mm][nn][0];
            o0.y = bv1 - 2.f * acc[mm][nn][1];
            o1.x = bv0 - 2.f * acc[mm][nn][2];
            o1.y = bv1 - 2.f * acc[mm][nn][3];
            *(float2*)(C + (size_t)row * NN + col)       = o0;
            *(float2*)(C + (size_t)(row + 8) * NN + col) = o1;
        }
    }

    if (bi != bj) {
        float* Sc = sm;
        #pragma unroll
        for (int mm = 0; mm < 4; mm++) {
            const int lr = warp_m * 64 + mm * 16 + g;
            const float s0 = sq[row0 + lr], s1 = sq[row0 + lr + 8];
            #pragma unroll
            for (int nn = 0; nn < 4; nn++) {
                const int lc = warp_n * 32 + nn * 8 + tg * 2;
                Sc[lc * 132 + lr]            = s0 - 2.f * acc[mm][nn][0];
                Sc[(lc + 1) * 132 + lr]      = s0 - 2.f * acc[mm][nn][1];
                Sc[lc * 132 + lr + 8]        = s1 - 2.f * acc[mm][nn][2];
                Sc[(lc + 1) * 132 + lr + 8]  = s1 - 2.f * acc[mm][nn][3];
            }
        }
        __syncthreads();
        #pragma unroll
        for (int it = 0; it < 16; it++) {
            const int lc = warp + it * 8;
            const float4 v = *(const float4*)&Sc[lc * 132 + lane * 4];
            *(float4*)(C + (size_t)(col0 + lc) * NN + row0 + lane * 4) = v;
        }
    }
}

// ---------------- fallback SIMT GEMM (used only when N % 128 != 0) ----------
#define GBM 128
#define GBN 64
#define GBK 32

__global__ __launch_bounds__(256, 2) void gemm_k(
    const float* __restrict__ A, const float* __restrict__ B,
    const float* __restrict__ bias, float* __restrict__ C,
    int M, int K, int N, int mode)
{
    __shared__ float As[GBK][GBM + 4];
    __shared__ float Bs[GBK][GBN];
    const int tid  = threadIdx.x;
    const int row0 = blockIdx.y * GBM;
    const int col0 = blockIdx.x * GBN;
    const int tr = tid >> 4;
    const int tc = tid & 15;

    float acc[8][4];
    #pragma unroll
    for (int i = 0; i < 8; i++)
        #pragma unroll
        for (int j = 0; j < 4; j++) acc[i][j] = 0.f;

    const int ktiles = K / GBK;
    for (int kt = 0; kt < ktiles; kt++) {
        #pragma unroll
        for (int p = 0; p < 4; p++) {
            int lin = tid + 256 * p;
            int r = lin >> 3, q = lin & 7;
            const float4 v = *(const float4*)(A + (size_t)(row0 + r) * K + kt * GBK + q * 4);
            As[q * 4 + 0][r] = v.x; As[q * 4 + 1][r] = v.y;
            As[q * 4 + 2][r] = v.z; As[q * 4 + 3][r] = v.w;
        }
        #pragma unroll
        for (int p = 0; p < 2; p++) {
            int lin = tid + 256 * p;
            int kr = lin >> 4, j4 = lin & 15;
            *(float4*)&Bs[kr][j4 * 4] =
                *(const float4*)(B + (size_t)(kt * GBK + kr) * N + col0 + j4 * 4);
        }
        __syncthreads();
        #pragma unroll
        for (int k = 0; k < GBK; k++) {
            float a[8], b[4];
            *(float4*)&a[0] = *(const float4*)&As[k][tr * 8];
            *(float4*)&a[4] = *(const float4*)&As[k][tr * 8 + 4];
            *(float4*)&b[0] = *(const float4*)&Bs[k][tc * 4];
            #pragma unroll
            for (int i = 0; i < 8; i++)
                #pragma unroll
                for (int j = 0; j < 4; j++)
                    acc[i][j] = fmaf(a[i], b[j], acc[i][j]);
        }
        __syncthreads();
    }

    float bv[4];
    #pragma unroll
    for (int j = 0; j < 4; j++) bv[j] = bias[col0 + tc * 4 + j];

    #pragma unroll
    for (int i = 0; i < 8; i++) {
        const int row = row0 + tr * 8 + i;
        float4 o;
        o.x = fmaxf(acc[i][0] + bv[0], 0.f);
        o.y = fmaxf(acc[i][1] + bv[1], 0.f);
        o.z = fmaxf(acc[i][2] + bv[2], 0.f);
        o.w = fmaxf(acc[i][3] + bv[3], 0.f);
        *(float4*)(C + (size_t)row * N + col0 + tc * 4) = o;
    }
}

// ---------------- dynamic fusion (factored first MLP layer) ------------------
__global__ __launch_bounds__(256) void dyn_fuse_k(
    const float* __restrict__ Pd, const float* __restrict__ P2,
    const int* __restrict__ knn, const float* __restrict__ bias,
    float* __restrict__ hid)
{
    const int e  = blockIdx.x * 4 + (threadIdx.x >> 6);
    const int c4 = threadIdx.x & 63;
    const int i = e >> 4;
    const int j = knn[e];
    const float4 pd = *(const float4*)(Pd + (size_t)i * HH + c4 * 4);
    const float4 pj = *(const float4*)(P2 + (size_t)j * HH + c4 * 4);
    const float4 b  = *(const float4*)(bias + c4 * 4);
    float4 o;
    o.x = fmaxf(pd.x + pj.x + b.x, 0.f);
    o.y = fmaxf(pd.y + pj.y + b.y, 0.f);
    o.z = fmaxf(pd.z + pj.z + b.z, 0.f);
    o.w = fmaxf(pd.w + pj.w + b.w, 0.f);
    *(float4*)(hid + (size_t)e * HH + c4 * 4) = o;
}

// Wd = W_top - W_bot  (DD*HH elements)
__global__ void wdiff_k(const float* __restrict__ W1, float* __restrict__ Wd)
{
    const int idx = blockIdx.x * 256 + threadIdx.x;
    Wd[idx] = W1[idx] - W1[DD * HH + idx];
}

// ---------------- small helper kernels --------------------------------------
__global__ void rownorm_k(const float* __restrict__ x, float* __restrict__ sq)
{
    const int row  = blockIdx.x * 8 + (threadIdx.x >> 5);
    const int lane = threadIdx.x & 31;
    const float* p = x + (size_t)row * DD;
    float s = 0.f;
    #pragma unroll
    for (int q = 0; q < 4; q++) { float v = p[lane + 32 * q]; s = fmaf(v, v, s); }
    #pragma unroll
    for (int o = 16; o > 0; o >>= 1) s += __shfl_xor_sync(0xffffffffu, s, o);
    if (lane == 0) sq[row] = s;
}

__global__ void transpose_k(const float* __restrict__ in, float* __restrict__ out)
{
    __shared__ float t[32][33];
    const int j0 = blockIdx.x * 32, k0 = blockIdx.y * 32;
    for (int r = threadIdx.y; r < 32; r += 8)
        t[r][threadIdx.x] = in[(size_t)(j0 + r) * DD + k0 + threadIdx.x];
    __syncthreads();
    for (int r = threadIdx.y; r < 32; r += 8)
        out[(size_t)(k0 + r) * NN + j0 + threadIdx.x] = t[threadIdx.x][r];
}

// ---------------- top-16: u64 keys, SLOT-MAJOR smem queues -------------------
__global__ __launch_bounds__(256) void topk_k(const float* __restrict__ dist,
                                              int* __restrict__ knn)
{
    __shared__ unsigned long long sk[KK * 256];   // 32 KB, slot-major
    const unsigned long long SENT = 0xFF800000FFFFFFFFull;  // (+inf, idxmax)
    const int tid = threadIdx.x;
    const int rr  = tid >> 4;          // row within block
    const int tt  = tid & 15;          // thread within row
    const int row_g = blockIdx.x * 16 + rr;
    const float* row = dist + (size_t)row_g * NN;

    #pragma unroll
    for (int q = 0; q < KK; q++) sk[q * 256 + tid] = SENT;
    unsigned long long worst_key = SENT;
    float worstf = __int_as_float(0x7f800000);   // +inf

    for (int c = 0; c < NN / 64; c++) {
        const float4 v = *(const float4*)(row + c * 64 + tt * 4);
        const float mn = fminf(fminf(v.x, v.y), fminf(v.z, v.w));
        if (mn <= worstf) {
            const int j0 = c * 64 + tt * 4;
            const float vv[4] = { v.x, v.y, v.z, v.w };
            #pragma unroll
            for (int u = 0; u < 4; u++) {
                uint32_t ou = __float_as_uint(vv[u]);
                ou = (ou & 0x80000000u) ? ~ou : (ou | 0x80000000u);
                const unsigned long long key =
                    ((unsigned long long)ou << 32) | (uint32_t)(j0 + u);
                if (key < worst_key) {
                    int p = KK - 1;
                    while (p > 0 && sk[(p - 1) * 256 + tid] > key) {
                        sk[p * 256 + tid] = sk[(p - 1) * 256 + tid];
                        p--;
                    }
                    sk[p * 256 + tid] = key;
                    worst_key = sk[(KK - 1) * 256 + tid];
                    uint32_t wo = (uint32_t)(worst_key >> 32);
                    wo = (wo & 0x80000000u) ? (wo ^ 0x80000000u) : ~wo;
                    worstf = __uint_as_float(wo);
                }
            }
        }
    }

    for (int s = 8; s > 0; s >>= 1) {
        __syncthreads();
        if (tt < s) {
            const int ca = rr * 16 + tt;
            const int cb = rr * 16 + tt + s;
            unsigned long long out[KK];
            int pa = 0, pb = 0;
            #pragma unroll
            for (int q = 0; q < KK; q++) {
                const unsigned long long ka = sk[pa * 256 + ca];
                const unsigned long long kb = sk[pb * 256 + cb];
                if (ka <= kb) { out[q] = ka; pa++; }
                else          { out[q] = kb; pb++; }
            }
            #pragma unroll
            for (int q = 0; q < KK; q++) sk[q * 256 + ca] = out[q];
        }
    }
    __syncthreads();
    knn[row_g * KK + tt] = (int)(sk[tt * 256 + rr * 16] & 0xFFFFFFFFu);
}

__global__ void concat_k(const float* __restrict__ a, const float* __restrict__ b,
                         float* __restrict__ out)
{
    const int i = blockIdx.x, c = threadIdx.x;
    out[(size_t)i * 256 + c] = (c < DD) ? a[i * DD + c] : b[i * DD + c - DD];
}

// ---------------- host orchestration ---------------------------------------
static inline void gemm_s(cudaStream_t st, const float* A, const float* B,
                          const float* bias, float* C,
                          int M, int K, int N, int mode, const void* ei = nullptr,
                          const float* P = nullptr)
{
    if ((N % TBN) == 0 && (M % TBM) == 0) {
        dim3 g(N / TBN, M / TBM);
        mma3_gemm_k<<<g, 256, MMA3_SMEM_BYTES, st>>>(A, B, bias, C, M, K, N, mode, ei, P);
    } else {
        dim3 g(N / GBN, M / GBM);
        gemm_k<<<g, 256, 0, st>>>(A, B, bias, C, M, K, N, mode);
    }
}

extern "C" void kernel_launch(void* const* d_in, const int* in_sizes, int n_in,
                              void* d_out, int out_size)
{
    const float* x    = (const float*)d_in[0];
    const float* ea_i = (const float*)d_in[1];
    const float* sW1  = (const float*)d_in[2];
    const float* sb1  = (const float*)d_in[3];
    const float* sW2  = (const float*)d_in[4];
    const float* sb2  = (const float*)d_in[5];
    const float* uW1  = (const float*)d_in[6];
    const float* ub1  = (const float*)d_in[7];
    const float* uW2  = (const float*)d_in[8];
    const float* ub2  = (const float*)d_in[9];
    const float* rW   = (const float*)d_in[10];
    const float* rb   = (const float*)d_in[11];
    const float* dW1  = (const float*)d_in[12];
    const float* db1  = (const float*)d_in[13];
    const float* dW2  = (const float*)d_in[14];
    const float* db2  = (const float*)d_in[15];
    const float* dUW1 = (const float*)d_in[16];
    const float* dUb1 = (const float*)d_in[17];
    const float* dUW2 = (const float*)d_in[18];
    const float* dUb2 = (const float*)d_in[19];
    const float* fW1  = (const float*)d_in[20];
    const float* fb1  = (const float*)d_in[21];
    const float* fW2  = (const float*)d_in[22];
    const float* fb2  = (const float*)d_in[23];
    const void*  ei   = d_in[24];

    cudaFuncSetAttribute(mma3_gemm_k, cudaFuncAttributeMaxDynamicSharedMemorySize,
                         MMA3_SMEM_BYTES);
    cudaFuncSetAttribute(dist_sym_k, cudaFuncAttributeMaxDynamicSharedMemorySize,
                         MMA3_SMEM_BYTES);

    // one-time side stream + fork/join events (host resources, not device mem;
    // identical GPU work on every call)
    static cudaStream_t s1 = nullptr;
    static cudaEvent_t  ev_fork = nullptr, ev_join = nullptr;
    if (!s1) {
        cudaStreamCreateWithFlags(&s1, cudaStreamNonBlocking);
        cudaEventCreateWithFlags(&ev_fork, cudaEventDisableTiming);
        cudaEventCreateWithFlags(&ev_join, cudaEventDisableTiming);
    }

    float *msg, *ea0, *ea1, *xs0, *xs1, *agg, *tmpN;
    float *msg2, *xd0, *xd1, *agg2, *Pd, *P2, *sq, *xT, *dist, *Wd;
    float *cat, *zero;
    int   *knn;
    cudaGetSymbolAddress((void**)&msg,  g_msg);
    cudaGetSymbolAddress((void**)&ea0,  g_ea0);
    cudaGetSymbolAddress((void**)&ea1,  g_ea1);
    cudaGetSymbolAddress((void**)&xs0,  g_xs0);
    cudaGetSymbolAddress((void**)&xs1,  g_xs1);
    cudaGetSymbolAddress((void**)&agg,  g_agg);
    cudaGetSymbolAddress((void**)&tmpN, g_tmpN);
    cudaGetSymbolAddress((void**)&msg2, g_msg2);
    cudaGetSymbolAddress((void**)&xd0,  g_xd0);
    cudaGetSymbolAddress((void**)&xd1,  g_xd1);
    cudaGetSymbolAddress((void**)&agg2, g_agg2);
    cudaGetSymbolAddress((void**)&Pd,   g_Pd);
    cudaGetSymbolAddress((void**)&P2,   g_P2);
    cudaGetSymbolAddress((void**)&sq,   g_sq);
    cudaGetSymbolAddress((void**)&xT,   g_xT);
    cudaGetSymbolAddress((void**)&dist, g_dist);
    cudaGetSymbolAddress((void**)&Wd,   g_Wd);
    cudaGetSymbolAddress((void**)&cat,  g_cat);
    cudaGetSymbolAddress((void**)&zero, g_zero);
    cudaGetSymbolAddress((void**)&knn,  g_knn);

    // fork: dynamic branch depends only on input x (never on ei)
    cudaEventRecord(ev_fork, 0);
    cudaStreamWaitEvent(s1, ev_fork, 0);

    detect_ei_k<<<1, 1>>>(ei);

    // ---------------- dynamic branch on s1: 2 kNN conv layers ---------------
    {
        const float* xd_in = x;
        float* xd_bufs[2] = { xd0, xd1 };
        for (int i = 0; i < 2; i++) {
            rownorm_k<<<NN / 8, 256, 0, s1>>>(xd_in, sq);
            transpose_k<<<dim3(NN / 32, DD / 32), dim3(32, 8), 0, s1>>>(xd_in, xT);
            dist_sym_k<<<dim3(NN / TBM, NN / TBM), 256, MMA3_SMEM_BYTES, s1>>>(
                xd_in, xT, sq, dist);
            topk_k<<<NN / 16, 256, 0, s1>>>(dist, knn);
            const float* W1 = dW1 + (size_t)i * 2 * DD * HH;
            wdiff_k<<<DD * HH / 256, 256, 0, s1>>>(W1, Wd);
            gemm_s(s1, xd_in, Wd, zero, Pd, NN, DD, HH, 2);
            gemm_s(s1, xd_in, W1 + (size_t)DD * HH, zero, P2, NN, DD, HH, 2);
            dyn_fuse_k<<<NE / 4, 256, 0, s1>>>(Pd, P2, knn, db1 + i * HH, msg2);
            cudaMemsetAsync(agg2, 0, (size_t)NN * DD * sizeof(float), s1);
            gemm_s(s1, msg2, dW2 + (size_t)i * HH * DD, db2 + i * DD, agg2, NE, HH, DD, 4);
            gemm_s(s1, agg2, dUW1 + (size_t)i * DD * HH, dUb1 + i * HH, Pd, NN, DD, HH, 0);
            float* xd_out = xd_bufs[i];
            gemm_s(s1, Pd, dUW2 + (size_t)i * HH * DD, dUb2 + i * DD, xd_out, NN, HH, DD, 0);
            xd_in = xd_out;
        }
    }

    // ---------------- static branch on stream 0: 3 conv layers --------------
    const float* xs_in = x;
    const float* ea_in = ea_i;
    float* xs_bufs[2] = { xs0, xs1 };
    float* ea_bufs[2] = { ea0, ea1 };
    for (int i = 0; i < 3; i++) {
        const float* W1 = sW1 + (size_t)i * 192 * HH;
        gemm_s(0, xs_in, W1 + (size_t)DE * HH, zero, tmpN, NN, DD, HH, 2);
        gemm_s(0, ea_in, W1, sb1 + i * HH, msg, NE, DE, HH, 5, ei, tmpN);
        cudaMemsetAsync(agg, 0, (size_t)NN * DD * sizeof(float));
        gemm_s(0, msg, sW2 + (size_t)i * HH * DD, sb2 + i * DD, agg, NE, HH, DD, 3, ei);
        gemm_s(0, agg,  uW1 + (size_t)i * DD * HH, ub1 + i * HH, tmpN, NN, DD, HH, 0);
        float* xs_out = xs_bufs[i & 1];
        gemm_s(0, tmpN, uW2 + (size_t)i * HH * DD, ub2 + i * DD, xs_out, NN, HH, DD, 0);
        if (i < 2) {
            float* ea_out = ea_bufs[i & 1];
            gemm_s(0, ea_in, rW + (size_t)i * DE * DE, rb + i * DE, ea_out, NE, DE, DE, 0);
            ea_in = ea_out;
        }
        xs_in = xs_out;
    }

    // join: fuse needs both branches
    cudaEventRecord(ev_join, s1);
    cudaStreamWaitEvent(0, ev_join, 0);

    const float* xd_fin = xd1;   // layer 1 output buffer
    concat_k<<<NN, 256>>>(xs_in, xd_fin, cat);
    gemm_s(0, cat,  fW1, fb1, tmpN, NN, 2 * DD, HH, 0);
    gemm_s(0, tmpN, fW2, fb2, (float*)d_out, NN, HH, DD, 0);
}